// round 1
// baseline (speedup 1.0000x reference)
#include <cuda_runtime.h>
#include <cuda_bf16.h>
#include <cstdint>
#include <cstddef>

// Problem constants
#define PB 16
#define PS 2048
#define PI 1024
#define PH 1024

// ---------------- scratch (device globals; no allocs allowed) ----------------
__device__ float g_gi[(size_t)PB * PS * (3 * PH)];   // [B*S, 3H]
__device__ float g_rnn[(size_t)PB * PS * PH];        // [B*S, H]
__device__ float g_hbuf[2][PB * PH];                 // ping-pong hidden state
__device__ unsigned g_bar_cnt;                       // zero-init
__device__ unsigned g_bar_gen;                       // zero-init

// ---------------- fp32 tiled GEMM: C[M,N] = A[M,K] @ B[N,K]^T + bias[N] -----
// M,N divisible by 128; K divisible by 16.
__global__ void __launch_bounds__(256)
sgemm_bt_bias(const float* __restrict__ A, const float* __restrict__ B,
              const float* __restrict__ bias, float* __restrict__ C,
              int M, int N, int K)
{
    const int BM = 128, BN = 128, BK = 16;
    __shared__ float As[BK][BM];
    __shared__ float Bs[BK][BN];

    const int tid = threadIdx.x;
    const int bm = blockIdx.y, bn = blockIdx.x;

    const int lr = tid >> 2;          // 0..63
    const int lc = (tid & 3) << 2;    // 0,4,8,12
    const float* Ablk = A + (size_t)(bm * BM) * K;
    const float* Bblk = B + (size_t)(bn * BN) * K;

    const int tr = tid >> 4;          // 0..15
    const int tc = tid & 15;          // 0..15

    float acc[8][8];
    #pragma unroll
    for (int i = 0; i < 8; i++)
        #pragma unroll
        for (int j = 0; j < 8; j++) acc[i][j] = 0.f;

    for (int k0 = 0; k0 < K; k0 += BK) {
        #pragma unroll
        for (int s = 0; s < 2; ++s) {
            int row = lr + s * 64;
            float4 v = *(const float4*)(Ablk + (size_t)row * K + k0 + lc);
            As[lc + 0][row] = v.x; As[lc + 1][row] = v.y;
            As[lc + 2][row] = v.z; As[lc + 3][row] = v.w;
            float4 w = *(const float4*)(Bblk + (size_t)row * K + k0 + lc);
            Bs[lc + 0][row] = w.x; Bs[lc + 1][row] = w.y;
            Bs[lc + 2][row] = w.z; Bs[lc + 3][row] = w.w;
        }
        __syncthreads();

        #pragma unroll
        for (int k = 0; k < BK; ++k) {
            float ra[8], rb[8];
            float4 a0 = *(const float4*)&As[k][tr * 8];
            float4 a1 = *(const float4*)&As[k][tr * 8 + 4];
            ra[0]=a0.x; ra[1]=a0.y; ra[2]=a0.z; ra[3]=a0.w;
            ra[4]=a1.x; ra[5]=a1.y; ra[6]=a1.z; ra[7]=a1.w;
            float4 b0 = *(const float4*)&Bs[k][tc * 8];
            float4 b1 = *(const float4*)&Bs[k][tc * 8 + 4];
            rb[0]=b0.x; rb[1]=b0.y; rb[2]=b0.z; rb[3]=b0.w;
            rb[4]=b1.x; rb[5]=b1.y; rb[6]=b1.z; rb[7]=b1.w;
            #pragma unroll
            for (int i = 0; i < 8; i++)
                #pragma unroll
                for (int j = 0; j < 8; j++)
                    acc[i][j] = fmaf(ra[i], rb[j], acc[i][j]);
        }
        __syncthreads();
    }

    #pragma unroll
    for (int i = 0; i < 8; i++) {
        int row = bm * BM + tr * 8 + i;
        #pragma unroll
        for (int j = 0; j < 8; j += 4) {
            int col = bn * BN + tc * 8 + j;
            float4 v;
            v.x = acc[i][j + 0] + bias[col + 0];
            v.y = acc[i][j + 1] + bias[col + 1];
            v.z = acc[i][j + 2] + bias[col + 2];
            v.w = acc[i][j + 3] + bias[col + 3];
            *(float4*)(C + (size_t)row * N + col) = v;
        }
    }
}

// ---------------- persistent GRU recurrence ----------------------------------
#define RG  128     // CTAs (<= SM count, 1 CTA/SM via smem -> co-resident)
#define CPC 8       // hidden columns per CTA (RG*CPC == PH)
#define RTH 256     // threads per CTA (8 warps; warp w owns column g*CPC+w)

__device__ __forceinline__ void grid_barrier(unsigned& gen)
{
    __threadfence();
    __syncthreads();
    if (threadIdx.x == 0) {
        unsigned arrived = atomicAdd(&g_bar_cnt, 1u);
        if (arrived == RG - 1) {
            g_bar_cnt = 0;
            __threadfence();
            atomicAdd(&g_bar_gen, 1u);
        } else {
            for (;;) {
                unsigned cur;
                asm volatile("ld.acquire.gpu.global.u32 %0, [%1];"
                             : "=r"(cur) : "l"(&g_bar_gen));
                if (cur - gen != 0u) break;
                __nanosleep(32);
            }
        }
        gen += 1u;
    }
    __syncthreads();
}

__global__ void __launch_bounds__(RTH, 1)
gru_persistent(const float* __restrict__ gi, const float* __restrict__ w_hh,
               const float* __restrict__ b_hh, float* __restrict__ rnn_out,
               float* __restrict__ hidden_out)
{
    extern __shared__ float sm[];
    float* sw = sm;                        // [3][CPC][PH]  weights (96 KB)
    float* sh = sm + 3 * CPC * PH;         // [PB][PH]      hidden  (64 KB)
    float* sb = sh + PB * PH;              // [3*CPC]       b_hh slice

    const int tid  = threadIdx.x;
    const int g    = blockIdx.x;
    const int warp = tid >> 5;
    const int lane = tid & 31;
    const int j    = g * CPC + warp;       // hidden column owned by this warp

    // ---- load w_hh slice into smem (rows j, H+j, 2H+j for each owned j) ----
    {
        const float4* w4 = (const float4*)w_hh;
        for (int idx = tid; idx < 3 * CPC * (PH / 4); idx += RTH) {
            int r    = idx / (PH / 4);     // 0..23 = gate*CPC + jl
            int c4   = idx % (PH / 4);
            int gate = r / CPC, jl = r % CPC;
            ((float4*)sw)[r * (PH / 4) + c4] =
                w4[((size_t)gate * PH + (size_t)g * CPC + jl) * (PH / 4) + c4];
        }
        if (tid < 3 * CPC) {
            int gate = tid / CPC, jl = tid % CPC;
            sb[tid] = b_hh[gate * PH + g * CPC + jl];
        }
    }
    // ---- zero initial hidden state (buf 0), split across CTAs ----
    {
        const int per = (PB * PH) / RG;    // 128
        for (int i = tid; i < per; i += RTH)
            g_hbuf[0][g * per + i] = 0.f;
    }

    unsigned gen;
    if (tid == 0) {
        asm volatile("ld.acquire.gpu.global.u32 %0, [%1];"
                     : "=r"(gen) : "l"(&g_bar_gen));
    }
    grid_barrier(gen);

    const float* wr = sw + (0 * CPC + warp) * PH;
    const float* wz = sw + (1 * CPC + warp) * PH;
    const float* wn = sw + (2 * CPC + warp) * PH;

    for (int t = 0; t < PS; ++t) {
        const float* hsrc = g_hbuf[t & 1];
        float* hdst = g_hbuf[(t + 1) & 1];

        // stage full h into smem (L2-only loads: other SMs wrote it last step)
        {
            const float4* h4 = (const float4*)hsrc;
            float4* sh4 = (float4*)sh;
            #pragma unroll
            for (int i = tid; i < (PB * PH) / 4; i += RTH)
                sh4[i] = __ldcg(h4 + i);
        }

        // prefetch gi for this (t, j) across batches (latency hidden by loop)
        float ir = 0.f, iz = 0.f, inn = 0.f;
        if (lane < PB) {
            const float* p = gi + ((size_t)lane * PS + t) * (3 * PH) + j;
            ir  = __ldg(p);
            iz  = __ldg(p + PH);
            inn = __ldg(p + 2 * PH);
        }
        __syncthreads();

        // gh partials: warp computes rows {j, H+j, 2H+j} x 16 batches
        float aR[PB], aZ[PB], aN[PB];
        #pragma unroll
        for (int b = 0; b < PB; b++) { aR[b] = 0.f; aZ[b] = 0.f; aN[b] = 0.f; }

        #pragma unroll 4
        for (int i = 0; i < PH / 32; ++i) {
            int k = i * 32 + lane;
            float vr = wr[k], vz = wz[k], vn = wn[k];
            #pragma unroll
            for (int b = 0; b < PB; ++b) {
                float hv = sh[b * PH + k];
                aR[b] = fmaf(vr, hv, aR[b]);
                aZ[b] = fmaf(vz, hv, aZ[b]);
                aN[b] = fmaf(vn, hv, aN[b]);
            }
        }
        // butterfly reduce across lanes (every lane ends with full sums)
        #pragma unroll
        for (int off = 16; off > 0; off >>= 1) {
            #pragma unroll
            for (int b = 0; b < PB; b++) {
                aR[b] += __shfl_xor_sync(0xFFFFFFFFu, aR[b], off);
                aZ[b] += __shfl_xor_sync(0xFFFFFFFFu, aZ[b], off);
                aN[b] += __shfl_xor_sync(0xFFFFFFFFu, aN[b], off);
            }
        }

        if (lane < PB) {
            float sr = 0.f, sz = 0.f, sn = 0.f;
            #pragma unroll
            for (int b = 0; b < PB; b++)
                if (lane == b) { sr = aR[b]; sz = aZ[b]; sn = aN[b]; }
            float hprev = sh[lane * PH + j];
            float r = 1.f / (1.f + expf(-(ir + sr + sb[0 * CPC + warp])));
            float z = 1.f / (1.f + expf(-(iz + sz + sb[1 * CPC + warp])));
            float n = tanhf(inn + r * (sn + sb[2 * CPC + warp]));
            float hnew = (1.f - z) * n + z * hprev;
            hdst[lane * PH + j] = hnew;
            rnn_out[((size_t)lane * PS + t) * PH + j] = hnew;
            if (t == PS - 1) hidden_out[lane * PH + j] = hnew;
        }
        grid_barrier(gen);
    }
}

// ---------------- attn = ones ------------------------------------------------
__global__ void fill_ones(float* __restrict__ p, int n)
{
    int i = blockIdx.x * blockDim.x + threadIdx.x;
    if (i < n) p[i] = 1.0f;
}

// ---------------- launch -----------------------------------------------------
extern "C" void kernel_launch(void* const* d_in, const int* in_sizes, int n_in,
                              void* d_out, int out_size)
{
    const float* x    = (const float*)d_in[0];
    // d_in[1..4] = attention params: mathematically dead (softmax over size-1 axis)
    const float* w_ih = (const float*)d_in[5];
    const float* w_hh = (const float*)d_in[6];
    const float* b_ih = (const float*)d_in[7];
    const float* b_hh = (const float*)d_in[8];
    const float* fc_w = (const float*)d_in[9];
    const float* fc_b = (const float*)d_in[10];

    float* out    = (float*)d_out;                       // [B*S, I]
    float* hidden = out + (size_t)PB * PS * PI;          // [B, H]
    float* attn   = hidden + (size_t)PB * PH;            // [B*S]

    float *gi_ptr = nullptr, *rnn_ptr = nullptr;
    cudaGetSymbolAddress((void**)&gi_ptr, g_gi);
    cudaGetSymbolAddress((void**)&rnn_ptr, g_rnn);

    const int M = PB * PS;   // 32768

    // 1) gi = x @ w_ih^T + b_ih   [32768, 3072]
    {
        dim3 grid((3 * PH) / 128, M / 128);
        sgemm_bt_bias<<<grid, 256>>>(x, w_ih, b_ih, gi_ptr, M, 3 * PH, PI);
    }

    // 2) persistent GRU scan
    {
        size_t smem = (size_t)(3 * CPC * PH + PB * PH + 3 * CPC + 8) * sizeof(float);
        cudaFuncSetAttribute(gru_persistent,
                             cudaFuncAttributeMaxDynamicSharedMemorySize,
                             (int)smem);
        gru_persistent<<<RG, RTH, smem>>>(gi_ptr, w_hh, b_hh, rnn_ptr, hidden);
    }

    // 3) output = rnn_out @ fc_w^T + fc_b   [32768, 1024]
    {
        dim3 grid(PI / 128, M / 128);
        sgemm_bt_bias<<<grid, 256>>>(rnn_ptr, fc_w, fc_b, out, M, PI, PH);
    }

    // 4) attn = 1.0
    {
        int n = PB * PS;
        fill_ones<<<(n + 255) / 256, 256>>>(attn, n);
    }
}

// round 2
// speedup vs baseline: 1.2482x; 1.2482x over previous
#include <cuda_runtime.h>
#include <cuda_bf16.h>
#include <cstdint>
#include <cstddef>

// Problem constants
#define PB 16
#define PS 2048
#define PI 1024
#define PH 1024

// ---------------- scratch (device globals; no allocs allowed) ----------------
__device__ float g_gi[(size_t)PB * PS * (3 * PH)];   // [B*S, 3H]
__device__ float g_rnn[(size_t)PB * PS * PH];        // [B*S, H] (tf32-rounded)
__device__ float g_xr[(size_t)PB * PS * PI];         // tf32-rounded x
__device__ float g_wihr[(size_t)(3 * PH) * PI];      // tf32-rounded w_ih
__device__ float g_fcwr[(size_t)PI * PH];            // tf32-rounded fc_w
__device__ float g_hbuf[2][PB * PH];                 // ping-pong hidden state
__device__ unsigned g_bar_cnt;                       // zero-init
__device__ unsigned g_bar_gen;                       // zero-init

// ---------------- tf32 rounding prepass --------------------------------------
__global__ void __launch_bounds__(256)
round_tf32(const float* __restrict__ src, float* __restrict__ dst, int n4)
{
    int i = blockIdx.x * blockDim.x + threadIdx.x;
    int stride = gridDim.x * blockDim.x;
    for (; i < n4; i += stride) {
        float4 v = ((const float4*)src)[i];
        float4 o;
        asm("cvt.rna.tf32.f32 %0, %1;" : "=f"(o.x) : "f"(v.x));
        asm("cvt.rna.tf32.f32 %0, %1;" : "=f"(o.y) : "f"(v.y));
        asm("cvt.rna.tf32.f32 %0, %1;" : "=f"(o.z) : "f"(v.z));
        asm("cvt.rna.tf32.f32 %0, %1;" : "=f"(o.w) : "f"(v.w));
        ((float4*)dst)[i] = o;
    }
}

// ---------------- tf32 tensor-core GEMM: C = A[M,K] @ B[N,K]^T + bias --------
// A, B must be pre-rounded to tf32-representable fp32.
// M,N divisible by 128, K divisible by 32.
#define GPAD 36            // smem row stride (floats) -> conflict-free frags

__device__ __forceinline__ void cp_async16(float* smem, const float* gmem)
{
    uint32_t s = (uint32_t)__cvta_generic_to_shared(smem);
    asm volatile("cp.async.cg.shared.global [%0], [%1], 16;" :: "r"(s), "l"(gmem));
}

__global__ void __launch_bounds__(256, 2)
gemm_tf32_bt_bias(const float* __restrict__ A, const float* __restrict__ B,
                  const float* __restrict__ bias, float* __restrict__ C,
                  int M, int N, int K)
{
    extern __shared__ float smem[];
    // per stage: A 128xGPAD (4608 f) + B 128xGPAD (4608 f) = 9216 floats
    const int STG = 9216;

    const int tid  = threadIdx.x;
    const int wid  = tid >> 5;
    const int lane = tid & 31;
    const int wm   = wid >> 1;          // 0..3  (warp row)
    const int wn   = wid & 1;           // 0..1  (warp col)
    const int fr   = lane >> 2;         // 0..7
    const int fc   = lane & 3;          // 0..3

    const int bm = blockIdx.y, bn = blockIdx.x;
    const float* Ag = A + (size_t)(bm * 128) * K;
    const float* Bg = B + (size_t)(bn * 128) * K;

    const int NIT = K / 32;

    // issue load for stage 0
    {
        float* sA = smem;
        float* sB = smem + 4608;
        #pragma unroll
        for (int i = 0; i < 4; i++) {
            int idx = tid + i * 256;
            int row = idx >> 3, c4 = (idx & 7) << 2;
            cp_async16(sA + row * GPAD + c4, Ag + (size_t)row * K + c4);
            cp_async16(sB + row * GPAD + c4, Bg + (size_t)row * K + c4);
        }
        asm volatile("cp.async.commit_group;");
    }

    float acc[2][8][4];
    #pragma unroll
    for (int mt = 0; mt < 2; mt++)
        #pragma unroll
        for (int nt = 0; nt < 8; nt++)
            #pragma unroll
            for (int r = 0; r < 4; r++) acc[mt][nt][r] = 0.f;

    for (int it = 0; it < NIT; ++it) {
        asm volatile("cp.async.wait_group 0;");
        __syncthreads();

        // issue next stage load (buffer it+1 mod 2; its old reader synced above)
        if (it + 1 < NIT) {
            float* sA = smem + ((it + 1) & 1) * STG;
            float* sB = sA + 4608;
            const float* Agt = Ag + (size_t)(it + 1) * 32;
            const float* Bgt = Bg + (size_t)(it + 1) * 32;
            #pragma unroll
            for (int i = 0; i < 4; i++) {
                int idx = tid + i * 256;
                int row = idx >> 3, c4 = (idx & 7) << 2;
                cp_async16(sA + row * GPAD + c4, Agt + (size_t)row * K + c4);
                cp_async16(sB + row * GPAD + c4, Bgt + (size_t)row * K + c4);
            }
            asm volatile("cp.async.commit_group;");
        }

        const float* sA = smem + (it & 1) * STG;
        const float* sB = sA + 4608;

        #pragma unroll
        for (int kk = 0; kk < 32; kk += 8) {
            uint32_t a[2][4], b[8][2];
            #pragma unroll
            for (int mt = 0; mt < 2; mt++) {
                int r0 = wm * 32 + mt * 16 + fr;
                a[mt][0] = __float_as_uint(sA[(r0    ) * GPAD + kk +     fc]);
                a[mt][1] = __float_as_uint(sA[(r0 + 8) * GPAD + kk +     fc]);
                a[mt][2] = __float_as_uint(sA[(r0    ) * GPAD + kk + 4 + fc]);
                a[mt][3] = __float_as_uint(sA[(r0 + 8) * GPAD + kk + 4 + fc]);
            }
            #pragma unroll
            for (int nt = 0; nt < 8; nt++) {
                int c0 = wn * 64 + nt * 8 + fr;
                b[nt][0] = __float_as_uint(sB[c0 * GPAD + kk +     fc]);
                b[nt][1] = __float_as_uint(sB[c0 * GPAD + kk + 4 + fc]);
            }
            #pragma unroll
            for (int mt = 0; mt < 2; mt++)
                #pragma unroll
                for (int nt = 0; nt < 8; nt++) {
                    asm volatile(
                        "mma.sync.aligned.m16n8k8.row.col.f32.tf32.tf32.f32 "
                        "{%0,%1,%2,%3}, {%4,%5,%6,%7}, {%8,%9}, {%0,%1,%2,%3};"
                        : "+f"(acc[mt][nt][0]), "+f"(acc[mt][nt][1]),
                          "+f"(acc[mt][nt][2]), "+f"(acc[mt][nt][3])
                        : "r"(a[mt][0]), "r"(a[mt][1]), "r"(a[mt][2]), "r"(a[mt][3]),
                          "r"(b[nt][0]), "r"(b[nt][1]));
                }
        }
        __syncthreads();
    }

    // epilogue: bias + store
    #pragma unroll
    for (int mt = 0; mt < 2; mt++) {
        int row = bm * 128 + wm * 32 + mt * 16 + fr;
        #pragma unroll
        for (int nt = 0; nt < 8; nt++) {
            int col = bn * 128 + wn * 64 + nt * 8 + 2 * fc;
            float b0 = bias[col], b1 = bias[col + 1];
            float2 v0 = make_float2(acc[mt][nt][0] + b0, acc[mt][nt][1] + b1);
            float2 v1 = make_float2(acc[mt][nt][2] + b0, acc[mt][nt][3] + b1);
            *(float2*)(C + (size_t)row * N + col)       = v0;
            *(float2*)(C + (size_t)(row + 8) * N + col) = v1;
        }
    }
}

// ---------------- persistent GRU recurrence ----------------------------------
#define RG  128     // CTAs (<= SM count, 1 CTA/SM via smem -> co-resident)
#define CPC 8       // hidden columns per CTA (RG*CPC == PH)
#define RTH 256     // threads per CTA (8 warps; warp w owns column g*CPC+w)

__device__ __forceinline__ void grid_barrier(unsigned& gen)
{
    __threadfence();
    __syncthreads();
    if (threadIdx.x == 0) {
        unsigned arrived = atomicAdd(&g_bar_cnt, 1u);
        if (arrived == RG - 1) {
            g_bar_cnt = 0;
            __threadfence();
            atomicAdd(&g_bar_gen, 1u);
        } else {
            for (;;) {
                unsigned cur;
                asm volatile("ld.acquire.gpu.global.u32 %0, [%1];"
                             : "=r"(cur) : "l"(&g_bar_gen));
                if (cur - gen != 0u) break;
                __nanosleep(32);
            }
        }
        gen += 1u;
    }
    __syncthreads();
}

__global__ void __launch_bounds__(RTH, 1)
gru_persistent(const float* __restrict__ gi, const float* __restrict__ w_hh,
               const float* __restrict__ b_hh, float* __restrict__ rnn_out,
               float* __restrict__ hidden_out)
{
    extern __shared__ float sm[];
    float* sw = sm;                        // [3][CPC][PH]  weights (96 KB)
    float* sh = sm + 3 * CPC * PH;         // [PB][PH]      hidden  (64 KB)
    float* sb = sh + PB * PH;              // [3*CPC]       b_hh slice

    const int tid  = threadIdx.x;
    const int g    = blockIdx.x;
    const int warp = tid >> 5;
    const int lane = tid & 31;
    const int j    = g * CPC + warp;       // hidden column owned by this warp

    // ---- load w_hh slice into smem (rows j, H+j, 2H+j for each owned j) ----
    {
        const float4* w4 = (const float4*)w_hh;
        for (int idx = tid; idx < 3 * CPC * (PH / 4); idx += RTH) {
            int r    = idx / (PH / 4);     // 0..23 = gate*CPC + jl
            int c4   = idx % (PH / 4);
            int gate = r / CPC, jl = r % CPC;
            ((float4*)sw)[r * (PH / 4) + c4] =
                w4[((size_t)gate * PH + (size_t)g * CPC + jl) * (PH / 4) + c4];
        }
        if (tid < 3 * CPC) {
            int gate = tid / CPC, jl = tid % CPC;
            sb[tid] = b_hh[gate * PH + g * CPC + jl];
        }
    }
    // ---- zero initial hidden state (buf 0), split across CTAs ----
    {
        const int per = (PB * PH) / RG;    // 128
        for (int i = tid; i < per; i += RTH)
            g_hbuf[0][g * per + i] = 0.f;
    }

    unsigned gen;
    if (tid == 0) {
        asm volatile("ld.acquire.gpu.global.u32 %0, [%1];"
                     : "=r"(gen) : "l"(&g_bar_gen));
    }
    grid_barrier(gen);

    const float* wr = sw + (0 * CPC + warp) * PH;
    const float* wz = sw + (1 * CPC + warp) * PH;
    const float* wn = sw + (2 * CPC + warp) * PH;

    for (int t = 0; t < PS; ++t) {
        const float* hsrc = g_hbuf[t & 1];
        float* hdst = g_hbuf[(t + 1) & 1];

        // stage full h into smem (L2-only loads: other SMs wrote it last step)
        {
            const float4* h4 = (const float4*)hsrc;
            float4* sh4 = (float4*)sh;
            #pragma unroll
            for (int i = tid; i < (PB * PH) / 4; i += RTH)
                sh4[i] = __ldcg(h4 + i);
        }

        // prefetch gi for this (t, j) across batches (latency hidden by loop)
        float ir = 0.f, iz = 0.f, inn = 0.f;
        if (lane < PB) {
            const float* p = gi + ((size_t)lane * PS + t) * (3 * PH) + j;
            ir  = __ldg(p);
            iz  = __ldg(p + PH);
            inn = __ldg(p + 2 * PH);
        }
        __syncthreads();

        // gh partials: warp computes rows {j, H+j, 2H+j} x 16 batches
        float aR[PB], aZ[PB], aN[PB];
        #pragma unroll
        for (int b = 0; b < PB; b++) { aR[b] = 0.f; aZ[b] = 0.f; aN[b] = 0.f; }

        #pragma unroll 4
        for (int i = 0; i < PH / 32; ++i) {
            int k = i * 32 + lane;
            float vr = wr[k], vz = wz[k], vn = wn[k];
            #pragma unroll
            for (int b = 0; b < PB; ++b) {
                float hv = sh[b * PH + k];
                aR[b] = fmaf(vr, hv, aR[b]);
                aZ[b] = fmaf(vz, hv, aZ[b]);
                aN[b] = fmaf(vn, hv, aN[b]);
            }
        }
        // butterfly reduce across lanes (every lane ends with full sums)
        #pragma unroll
        for (int off = 16; off > 0; off >>= 1) {
            #pragma unroll
            for (int b = 0; b < PB; b++) {
                aR[b] += __shfl_xor_sync(0xFFFFFFFFu, aR[b], off);
                aZ[b] += __shfl_xor_sync(0xFFFFFFFFu, aZ[b], off);
                aN[b] += __shfl_xor_sync(0xFFFFFFFFu, aN[b], off);
            }
        }

        if (lane < PB) {
            float sr = 0.f, sz = 0.f, sn = 0.f;
            #pragma unroll
            for (int b = 0; b < PB; b++)
                if (lane == b) { sr = aR[b]; sz = aZ[b]; sn = aN[b]; }
            float hprev = sh[lane * PH + j];
            float r = 1.f / (1.f + expf(-(ir + sr + sb[0 * CPC + warp])));
            float z = 1.f / (1.f + expf(-(iz + sz + sb[1 * CPC + warp])));
            float n = tanhf(inn + r * (sn + sb[2 * CPC + warp]));
            float hnew = (1.f - z) * n + z * hprev;
            hdst[lane * PH + j] = hnew;
            // store rnn_out pre-rounded to tf32 (feeds fc tensor-core GEMM)
            float hr;
            asm("cvt.rna.tf32.f32 %0, %1;" : "=f"(hr) : "f"(hnew));
            rnn_out[((size_t)lane * PS + t) * PH + j] = hr;
            if (t == PS - 1) hidden_out[lane * PH + j] = hnew;
        }
        grid_barrier(gen);
    }
}

// ---------------- attn = ones ------------------------------------------------
__global__ void fill_ones(float* __restrict__ p, int n)
{
    int i = blockIdx.x * blockDim.x + threadIdx.x;
    if (i < n) p[i] = 1.0f;
}

// ---------------- launch -----------------------------------------------------
extern "C" void kernel_launch(void* const* d_in, const int* in_sizes, int n_in,
                              void* d_out, int out_size)
{
    const float* x    = (const float*)d_in[0];
    // d_in[1..4] = attention params: mathematically dead (softmax over size-1 axis)
    const float* w_ih = (const float*)d_in[5];
    const float* w_hh = (const float*)d_in[6];
    const float* b_ih = (const float*)d_in[7];
    const float* b_hh = (const float*)d_in[8];
    const float* fc_w = (const float*)d_in[9];
    const float* fc_b = (const float*)d_in[10];

    float* out    = (float*)d_out;                       // [B*S, I]
    float* hidden = out + (size_t)PB * PS * PI;          // [B, H]
    float* attn   = hidden + (size_t)PB * PH;            // [B*S]

    float *gi_ptr, *rnn_ptr, *xr_ptr, *wihr_ptr, *fcwr_ptr;
    cudaGetSymbolAddress((void**)&gi_ptr,   g_gi);
    cudaGetSymbolAddress((void**)&rnn_ptr,  g_rnn);
    cudaGetSymbolAddress((void**)&xr_ptr,   g_xr);
    cudaGetSymbolAddress((void**)&wihr_ptr, g_wihr);
    cudaGetSymbolAddress((void**)&fcwr_ptr, g_fcwr);

    const int M = PB * PS;   // 32768

    // 0) round inputs to tf32-representable fp32
    round_tf32<<<1184, 256>>>(x,    xr_ptr,   (PB * PS * PI) / 4);
    round_tf32<<<296,  256>>>(w_ih, wihr_ptr, (3 * PH * PI) / 4);
    round_tf32<<<296,  256>>>(fc_w, fcwr_ptr, (PI * PH) / 4);

    const size_t gsmem = 2 * 9216 * sizeof(float);  // 73728 B
    cudaFuncSetAttribute(gemm_tf32_bt_bias,
                         cudaFuncAttributeMaxDynamicSharedMemorySize, (int)gsmem);

    // 1) gi = x @ w_ih^T + b_ih   [32768, 3072]
    {
        dim3 grid((3 * PH) / 128, M / 128);
        gemm_tf32_bt_bias<<<grid, 256, gsmem>>>(xr_ptr, wihr_ptr, b_ih, gi_ptr,
                                                M, 3 * PH, PI);
    }

    // 2) persistent GRU scan
    {
        size_t smem = (size_t)(3 * CPC * PH + PB * PH + 3 * CPC + 8) * sizeof(float);
        cudaFuncSetAttribute(gru_persistent,
                             cudaFuncAttributeMaxDynamicSharedMemorySize,
                             (int)smem);
        gru_persistent<<<RG, RTH, smem>>>(gi_ptr, w_hh, b_hh, rnn_ptr, hidden);
    }

    // 3) output = rnn_out @ fc_w^T + fc_b   [32768, 1024]
    {
        dim3 grid(PI / 128, M / 128);
        gemm_tf32_bt_bias<<<grid, 256, gsmem>>>(rnn_ptr, fcwr_ptr, fc_b, out,
                                                M, PI, PH);
    }

    // 4) attn = 1.0
    {
        int n = PB * PS;
        fill_ones<<<(n + 255) / 256, 256>>>(attn, n);
    }
}

// round 3
// speedup vs baseline: 1.8415x; 1.4754x over previous
#include <cuda_runtime.h>
#include <cuda_bf16.h>
#include <cstdint>
#include <cstddef>

// Problem constants
#define PB 16
#define PS 2048
#define PI 1024
#define PH 1024

// ---------------- scratch (device globals; no allocs allowed) ----------------
__device__ float g_gi[(size_t)PB * PS * (3 * PH)];   // [B*S, 3H]
__device__ float g_rnn[(size_t)PB * PS * PH];        // [B*S, H] (tf32-rounded)
__device__ float g_xr[(size_t)PB * PS * PI];         // tf32-rounded x
__device__ float g_wihr[(size_t)(3 * PH) * PI];      // tf32-rounded w_ih
__device__ float g_fcwr[(size_t)PI * PH];            // tf32-rounded fc_w
__device__ float g_hbuf[2][PB * PH];                 // ping-pong hidden state
__device__ unsigned g_flags[128];                    // per-CTA step flags
__device__ unsigned g_bar_cnt;                       // zero-init
__device__ unsigned g_bar_gen;                       // zero-init

// ---------------- tf32 rounding prepass --------------------------------------
__global__ void __launch_bounds__(256)
round_tf32(const float* __restrict__ src, float* __restrict__ dst, int n4)
{
    int i = blockIdx.x * blockDim.x + threadIdx.x;
    int stride = gridDim.x * blockDim.x;
    for (; i < n4; i += stride) {
        float4 v = ((const float4*)src)[i];
        float4 o;
        asm("cvt.rna.tf32.f32 %0, %1;" : "=f"(o.x) : "f"(v.x));
        asm("cvt.rna.tf32.f32 %0, %1;" : "=f"(o.y) : "f"(v.y));
        asm("cvt.rna.tf32.f32 %0, %1;" : "=f"(o.z) : "f"(v.z));
        asm("cvt.rna.tf32.f32 %0, %1;" : "=f"(o.w) : "f"(v.w));
        ((float4*)dst)[i] = o;
    }
}

// ---------------- tf32 tensor-core GEMM: C = A[M,K] @ B[N,K]^T + bias --------
#define GPAD 36

__device__ __forceinline__ void cp_async16(float* smem, const float* gmem)
{
    uint32_t s = (uint32_t)__cvta_generic_to_shared(smem);
    asm volatile("cp.async.cg.shared.global [%0], [%1], 16;" :: "r"(s), "l"(gmem));
}

__global__ void __launch_bounds__(256, 2)
gemm_tf32_bt_bias(const float* __restrict__ A, const float* __restrict__ B,
                  const float* __restrict__ bias, float* __restrict__ C,
                  int M, int N, int K)
{
    extern __shared__ float smem[];
    const int STG = 9216;

    const int tid  = threadIdx.x;
    const int wid  = tid >> 5;
    const int lane = tid & 31;
    const int wm   = wid >> 1;
    const int wn   = wid & 1;
    const int fr   = lane >> 2;
    const int fc   = lane & 3;

    const int bm = blockIdx.y, bn = blockIdx.x;
    const float* Ag = A + (size_t)(bm * 128) * K;
    const float* Bg = B + (size_t)(bn * 128) * K;

    const int NIT = K / 32;

    {
        float* sA = smem;
        float* sB = smem + 4608;
        #pragma unroll
        for (int i = 0; i < 4; i++) {
            int idx = tid + i * 256;
            int row = idx >> 3, c4 = (idx & 7) << 2;
            cp_async16(sA + row * GPAD + c4, Ag + (size_t)row * K + c4);
            cp_async16(sB + row * GPAD + c4, Bg + (size_t)row * K + c4);
        }
        asm volatile("cp.async.commit_group;");
    }

    float acc[2][8][4];
    #pragma unroll
    for (int mt = 0; mt < 2; mt++)
        #pragma unroll
        for (int nt = 0; nt < 8; nt++)
            #pragma unroll
            for (int r = 0; r < 4; r++) acc[mt][nt][r] = 0.f;

    for (int it = 0; it < NIT; ++it) {
        asm volatile("cp.async.wait_group 0;");
        __syncthreads();

        if (it + 1 < NIT) {
            float* sA = smem + ((it + 1) & 1) * STG;
            float* sB = sA + 4608;
            const float* Agt = Ag + (size_t)(it + 1) * 32;
            const float* Bgt = Bg + (size_t)(it + 1) * 32;
            #pragma unroll
            for (int i = 0; i < 4; i++) {
                int idx = tid + i * 256;
                int row = idx >> 3, c4 = (idx & 7) << 2;
                cp_async16(sA + row * GPAD + c4, Agt + (size_t)row * K + c4);
                cp_async16(sB + row * GPAD + c4, Bgt + (size_t)row * K + c4);
            }
            asm volatile("cp.async.commit_group;");
        }

        const float* sA = smem + (it & 1) * STG;
        const float* sB = sA + 4608;

        #pragma unroll
        for (int kk = 0; kk < 32; kk += 8) {
            uint32_t a[2][4], b[8][2];
            #pragma unroll
            for (int mt = 0; mt < 2; mt++) {
                int r0 = wm * 32 + mt * 16 + fr;
                a[mt][0] = __float_as_uint(sA[(r0    ) * GPAD + kk +     fc]);
                a[mt][1] = __float_as_uint(sA[(r0 + 8) * GPAD + kk +     fc]);
                a[mt][2] = __float_as_uint(sA[(r0    ) * GPAD + kk + 4 + fc]);
                a[mt][3] = __float_as_uint(sA[(r0 + 8) * GPAD + kk + 4 + fc]);
            }
            #pragma unroll
            for (int nt = 0; nt < 8; nt++) {
                int c0 = wn * 64 + nt * 8 + fr;
                b[nt][0] = __float_as_uint(sB[c0 * GPAD + kk +     fc]);
                b[nt][1] = __float_as_uint(sB[c0 * GPAD + kk + 4 + fc]);
            }
            #pragma unroll
            for (int mt = 0; mt < 2; mt++)
                #pragma unroll
                for (int nt = 0; nt < 8; nt++) {
                    asm volatile(
                        "mma.sync.aligned.m16n8k8.row.col.f32.tf32.tf32.f32 "
                        "{%0,%1,%2,%3}, {%4,%5,%6,%7}, {%8,%9}, {%0,%1,%2,%3};"
                        : "+f"(acc[mt][nt][0]), "+f"(acc[mt][nt][1]),
                          "+f"(acc[mt][nt][2]), "+f"(acc[mt][nt][3])
                        : "r"(a[mt][0]), "r"(a[mt][1]), "r"(a[mt][2]), "r"(a[mt][3]),
                          "r"(b[nt][0]), "r"(b[nt][1]));
                }
        }
        __syncthreads();
    }

    #pragma unroll
    for (int mt = 0; mt < 2; mt++) {
        int row = bm * 128 + wm * 32 + mt * 16 + fr;
        #pragma unroll
        for (int nt = 0; nt < 8; nt++) {
            int col = bn * 128 + wn * 64 + nt * 8 + 2 * fc;
            float b0 = bias[col], b1 = bias[col + 1];
            float2 v0 = make_float2(acc[mt][nt][0] + b0, acc[mt][nt][1] + b1);
            float2 v1 = make_float2(acc[mt][nt][2] + b0, acc[mt][nt][3] + b1);
            *(float2*)(C + (size_t)row * N + col)       = v0;
            *(float2*)(C + (size_t)(row + 8) * N + col) = v1;
        }
    }
}

// ---------------- persistent GRU recurrence (tensor-core) --------------------
#define RG  128     // CTAs; 1 per SM, all co-resident
#define CPC 8       // hidden columns per CTA per gate
#define RTH 256     // 8 warps
#define SH_STRIDE 1036   // padded row stride for staged h (conflict-free frags)

__device__ __forceinline__ void grid_barrier_init(unsigned& gen)
{
    __threadfence();
    __syncthreads();
    if (threadIdx.x == 0) {
        unsigned arrived = atomicAdd(&g_bar_cnt, 1u);
        if (arrived == RG - 1) {
            g_bar_cnt = 0;
            __threadfence();
            atomicAdd(&g_bar_gen, 1u);
        } else {
            for (;;) {
                unsigned cur;
                asm volatile("ld.acquire.gpu.global.u32 %0, [%1];"
                             : "=r"(cur) : "l"(&g_bar_gen));
                if (cur - gen != 0u) break;
                __nanosleep(32);
            }
        }
        gen += 1u;
    }
    __syncthreads();
}

__global__ void __launch_bounds__(RTH, 1)
gru_persistent_tc(const float* __restrict__ gi, const float* __restrict__ w_hh,
                  const float* __restrict__ b_hh, float* __restrict__ rnn_out,
                  float* __restrict__ hidden_out)
{
    extern __shared__ float sm[];
    float* sh = sm;                       // [PB][SH_STRIDE] staged tf32 h
    float* sp = sm + PB * SH_STRIDE;      // [8][384] warp partials

    const int tid  = threadIdx.x;
    const int g    = blockIdx.x;
    const int warp = tid >> 5;
    const int lane = tid & 31;
    const int fr   = lane >> 2;           // 0..7
    const int fc   = lane & 3;            // 0..3
    const int colbase = g * CPC;

    // ---- resident B fragments: W_hh slice, tf32-rounded, in registers ----
    // warp w covers k in [w*128, (w+1)*128): 16 k-steps of 8
    uint32_t bf[3][16][2];
    #pragma unroll
    for (int gt = 0; gt < 3; gt++) {
        const float* wrow = w_hh + ((size_t)gt * PH + colbase + fr) * PH + warp * 128;
        #pragma unroll
        for (int ks = 0; ks < 16; ks++) {
            float v0 = __ldg(wrow + ks * 8 + fc);
            float v1 = __ldg(wrow + ks * 8 + 4 + fc);
            float r0, r1;
            asm("cvt.rna.tf32.f32 %0, %1;" : "=f"(r0) : "f"(v0));
            asm("cvt.rna.tf32.f32 %0, %1;" : "=f"(r1) : "f"(v1));
            bf[gt][ks][0] = __float_as_uint(r0);
            bf[gt][ks][1] = __float_as_uint(r1);
        }
    }

    // ---- epilogue thread mapping: tid<128 -> (b = tid>>3, jl = tid&7) ----
    const int eb = tid >> 3;
    const int ej = colbase + (tid & 7);
    float bias_r = 0.f, bias_z = 0.f, bias_n = 0.f;
    if (tid < 128) {
        bias_r = __ldg(b_hh + 0 * PH + ej);
        bias_z = __ldg(b_hh + 1 * PH + ej);
        bias_n = __ldg(b_hh + 2 * PH + ej);
    }

    // ---- reset flag + zero h0 slice, then one atomic init barrier ----
    if (tid == 0) g_flags[g] = 0u;
    {
        const int per = (PB * PH) / RG;    // 128
        for (int i = tid; i < per; i += RTH)
            g_hbuf[0][g * per + i] = 0.f;
    }
    unsigned gen;
    if (tid == 0) {
        asm volatile("ld.acquire.gpu.global.u32 %0, [%1];"
                     : "=r"(gen) : "l"(&g_bar_gen));
    }
    grid_barrier_init(gen);

    for (int t = 0; t < PS; ++t) {
        // prefetch gi (independent of h availability)
        float gir = 0.f, giz = 0.f, gin = 0.f;
        if (tid < 128) {
            const float* p = gi + ((size_t)eb * PS + t) * (3 * PH) + ej;
            gir = __ldg(p);
            giz = __ldg(p + PH);
            gin = __ldg(p + 2 * PH);
        }

        // wait until all CTAs have published h(t)
        if (warp == 0) {
            #pragma unroll
            for (int kk = 0; kk < 4; kk++) {
                const unsigned* fp = &g_flags[lane + 32 * kk];
                for (;;) {
                    unsigned v;
                    asm volatile("ld.acquire.gpu.global.u32 %0, [%1];"
                                 : "=r"(v) : "l"(fp));
                    if (v >= (unsigned)t) break;
                    __nanosleep(20);
                }
            }
        }
        __syncthreads();

        const float* hsrc = g_hbuf[t & 1];
        float* hdst = g_hbuf[(t + 1) & 1];

        // exact (unrounded) h_prev for the z*h path
        float hprev = 0.f;
        if (tid < 128) hprev = __ldcg(hsrc + eb * PH + ej);

        // stage h into smem, rounded to tf32 (L2 loads; L1 may be stale)
        {
            const float4* h4 = (const float4*)hsrc;
            #pragma unroll
            for (int i = 0; i < 16; i++) {
                int idx4 = tid + i * 256;
                float4 v = __ldcg(h4 + idx4);
                float4 o;
                asm("cvt.rna.tf32.f32 %0, %1;" : "=f"(o.x) : "f"(v.x));
                asm("cvt.rna.tf32.f32 %0, %1;" : "=f"(o.y) : "f"(v.y));
                asm("cvt.rna.tf32.f32 %0, %1;" : "=f"(o.z) : "f"(v.z));
                asm("cvt.rna.tf32.f32 %0, %1;" : "=f"(o.w) : "f"(v.w));
                int bb = idx4 >> 8;
                int cc = (idx4 & 255) << 2;
                *(float4*)(sh + bb * SH_STRIDE + cc) = o;
            }
        }
        __syncthreads();

        // MMA: acc[gt] = h[16, kslice] @ W_gt[8, kslice]^T  (per-warp k-slice)
        float acc[3][4];
        #pragma unroll
        for (int gt = 0; gt < 3; gt++)
            #pragma unroll
            for (int r = 0; r < 4; r++) acc[gt][r] = 0.f;

        #pragma unroll
        for (int ks = 0; ks < 16; ks++) {
            int k0 = warp * 128 + ks * 8 + fc;
            uint32_t a0 = __float_as_uint(sh[fr * SH_STRIDE + k0]);
            uint32_t a1 = __float_as_uint(sh[(fr + 8) * SH_STRIDE + k0]);
            uint32_t a2 = __float_as_uint(sh[fr * SH_STRIDE + k0 + 4]);
            uint32_t a3 = __float_as_uint(sh[(fr + 8) * SH_STRIDE + k0 + 4]);
            #pragma unroll
            for (int gt = 0; gt < 3; gt++) {
                asm volatile(
                    "mma.sync.aligned.m16n8k8.row.col.f32.tf32.tf32.f32 "
                    "{%0,%1,%2,%3}, {%4,%5,%6,%7}, {%8,%9}, {%0,%1,%2,%3};"
                    : "+f"(acc[gt][0]), "+f"(acc[gt][1]),
                      "+f"(acc[gt][2]), "+f"(acc[gt][3])
                    : "r"(a0), "r"(a1), "r"(a2), "r"(a3),
                      "r"(bf[gt][ks][0]), "r"(bf[gt][ks][1]));
            }
        }

        // store warp partials
        {
            float* pw = sp + warp * 384;
            #pragma unroll
            for (int gt = 0; gt < 3; gt++) {
                pw[gt * 128 + fr * 8 + 2 * fc]           = acc[gt][0];
                pw[gt * 128 + fr * 8 + 2 * fc + 1]       = acc[gt][1];
                pw[gt * 128 + (fr + 8) * 8 + 2 * fc]     = acc[gt][2];
                pw[gt * 128 + (fr + 8) * 8 + 2 * fc + 1] = acc[gt][3];
            }
        }
        __syncthreads();

        // reduce across warps + gate math + stores
        if (tid < 128) {
            float sr = 0.f, sz = 0.f, sn = 0.f;
            #pragma unroll
            for (int w = 0; w < 8; w++) {
                sr += sp[w * 384 +   0 + tid];
                sz += sp[w * 384 + 128 + tid];
                sn += sp[w * 384 + 256 + tid];
            }
            float r = 1.f / (1.f + expf(-(gir + sr + bias_r)));
            float z = 1.f / (1.f + expf(-(giz + sz + bias_z)));
            float n = tanhf(gin + r * (sn + bias_n));
            float hnew = (1.f - z) * n + z * hprev;
            hdst[eb * PH + ej] = hnew;
            float hr;
            asm("cvt.rna.tf32.f32 %0, %1;" : "=f"(hr) : "f"(hnew));
            rnn_out[((size_t)eb * PS + t) * PH + ej] = hr;
            if (t == PS - 1) hidden_out[eb * PH + ej] = hnew;
        }
        __syncthreads();
        if (tid == 0) {
            __threadfence();
            unsigned nv = (unsigned)(t + 1);
            asm volatile("st.release.gpu.global.u32 [%0], %1;"
                         :: "l"(&g_flags[g]), "r"(nv) : "memory");
        }
    }
}

// ---------------- attn = ones ------------------------------------------------
__global__ void fill_ones(float* __restrict__ p, int n)
{
    int i = blockIdx.x * blockDim.x + threadIdx.x;
    if (i < n) p[i] = 1.0f;
}

// ---------------- launch -----------------------------------------------------
extern "C" void kernel_launch(void* const* d_in, const int* in_sizes, int n_in,
                              void* d_out, int out_size)
{
    const float* x    = (const float*)d_in[0];
    // d_in[1..4] = attention params: dead (softmax over size-1 axis == 1)
    const float* w_ih = (const float*)d_in[5];
    const float* w_hh = (const float*)d_in[6];
    const float* b_ih = (const float*)d_in[7];
    const float* b_hh = (const float*)d_in[8];
    const float* fc_w = (const float*)d_in[9];
    const float* fc_b = (const float*)d_in[10];

    float* out    = (float*)d_out;                       // [B*S, I]
    float* hidden = out + (size_t)PB * PS * PI;          // [B, H]
    float* attn   = hidden + (size_t)PB * PH;            // [B*S]

    float *gi_ptr, *rnn_ptr, *xr_ptr, *wihr_ptr, *fcwr_ptr;
    cudaGetSymbolAddress((void**)&gi_ptr,   g_gi);
    cudaGetSymbolAddress((void**)&rnn_ptr,  g_rnn);
    cudaGetSymbolAddress((void**)&xr_ptr,   g_xr);
    cudaGetSymbolAddress((void**)&wihr_ptr, g_wihr);
    cudaGetSymbolAddress((void**)&fcwr_ptr, g_fcwr);

    const int M = PB * PS;   // 32768

    // 0) round GEMM inputs to tf32-representable fp32
    round_tf32<<<1184, 256>>>(x,    xr_ptr,   (PB * PS * PI) / 4);
    round_tf32<<<296,  256>>>(w_ih, wihr_ptr, (3 * PH * PI) / 4);
    round_tf32<<<296,  256>>>(fc_w, fcwr_ptr, (PI * PH) / 4);

    const size_t gsmem = 2 * 9216 * sizeof(float);
    cudaFuncSetAttribute(gemm_tf32_bt_bias,
                         cudaFuncAttributeMaxDynamicSharedMemorySize, (int)gsmem);

    // 1) gi = x @ w_ih^T + b_ih   [32768, 3072]
    {
        dim3 grid((3 * PH) / 128, M / 128);
        gemm_tf32_bt_bias<<<grid, 256, gsmem>>>(xr_ptr, wihr_ptr, b_ih, gi_ptr,
                                                M, 3 * PH, PI);
    }

    // 2) persistent tensor-core GRU scan
    {
        size_t smem = (size_t)(PB * SH_STRIDE + 8 * 384) * sizeof(float);
        cudaFuncSetAttribute(gru_persistent_tc,
                             cudaFuncAttributeMaxDynamicSharedMemorySize,
                             (int)smem);
        gru_persistent_tc<<<RG, RTH, smem>>>(gi_ptr, w_hh, b_hh, rnn_ptr, hidden);
    }

    // 3) output = rnn_out @ fc_w^T + fc_b   [32768, 1024]
    {
        dim3 grid(PI / 128, M / 128);
        gemm_tf32_bt_bias<<<grid, 256, gsmem>>>(rnn_ptr, fcwr_ptr, fc_b, out,
                                                M, PI, PH);
    }

    // 4) attn = 1.0
    {
        int n = PB * PS;
        fill_ones<<<(n + 255) / 256, 256>>>(attn, n);
    }
}

// round 4
// speedup vs baseline: 2.1286x; 1.1559x over previous
#include <cuda_runtime.h>
#include <cuda_fp16.h>
#include <cstdint>
#include <cstddef>

// Problem constants
#define PB 16
#define PS 2048
#define PI 1024
#define PH 1024

// ---------------- scratch (device globals; no allocs allowed) ----------------
__device__ float  g_gi[(size_t)PB * PS * (3 * PH)];   // [B*S, 3H] fp32
__device__ __half g_x16[(size_t)PB * PS * PI];
__device__ __half g_wih16[(size_t)(3 * PH) * PI];
__device__ __half g_fcw16[(size_t)PI * PH];
__device__ __half g_rnn16[(size_t)PB * PS * PH];
__device__ __half g_h16[2][PB * PH];                  // ping-pong hidden (fp16)
__device__ unsigned g_flags[128];
__device__ unsigned g_bar_cnt;
__device__ unsigned g_bar_gen;

// ---------------- fp32 -> fp16 prepass ---------------------------------------
__global__ void __launch_bounds__(256)
to_half(const float* __restrict__ src, __half* __restrict__ dst, int n4)
{
    int i = blockIdx.x * blockDim.x + threadIdx.x;
    int stride = gridDim.x * blockDim.x;
    for (; i < n4; i += stride) {
        float4 v = ((const float4*)src)[i];
        __half2 h0 = __floats2half2_rn(v.x, v.y);
        __half2 h1 = __floats2half2_rn(v.z, v.w);
        ((__half2*)dst)[2 * i]     = h0;
        ((__half2*)dst)[2 * i + 1] = h1;
    }
}

// ---------------- fp16 tensor-core GEMM: C = A[M,K] @ B[N,K]^T + bias --------
// smem row = 32 halves = 16 half2, padded stride GP2=20 half2.
#define GP2 20

__device__ __forceinline__ void cp_async16(void* smem, const void* gmem)
{
    uint32_t s = (uint32_t)__cvta_generic_to_shared(smem);
    asm volatile("cp.async.cg.shared.global [%0], [%1], 16;" :: "r"(s), "l"(gmem));
}

__global__ void __launch_bounds__(256, 2)
gemm_f16_bt_bias(const __half* __restrict__ A, const __half* __restrict__ B,
                 const float* __restrict__ bias, float* __restrict__ C,
                 int M, int N, int K)
{
    extern __shared__ __half2 smem2[];
    const int STG2 = 2 * 128 * GP2;      // A tile + B tile (half2) per stage

    const int tid  = threadIdx.x;
    const int wid  = tid >> 5;
    const int lane = tid & 31;
    const int wm   = wid >> 1;           // 0..3
    const int wn   = wid & 1;            // 0..1
    const int fr   = lane >> 2;          // 0..7
    const int fc   = lane & 3;           // 0..3

    const int bm = blockIdx.y, bn = blockIdx.x;
    const __half* Ag = A + (size_t)(bm * 128) * K;
    const __half* Bg = B + (size_t)(bn * 128) * K;

    const int NIT = K / 32;

    // stage 0 loads: 512 chunks of 16B per operand tile, 256 threads -> 2 each
    {
        __half2* sA = smem2;
        __half2* sB = smem2 + 128 * GP2;
        #pragma unroll
        for (int i = 0; i < 2; i++) {
            int idx = tid + i * 256;
            int row = idx >> 2, c = idx & 3;          // c*8 halves offset
            cp_async16(sA + row * GP2 + c * 4, Ag + (size_t)row * K + c * 8);
            cp_async16(sB + row * GP2 + c * 4, Bg + (size_t)row * K + c * 8);
        }
        asm volatile("cp.async.commit_group;");
    }

    float acc[2][8][4];
    #pragma unroll
    for (int mt = 0; mt < 2; mt++)
        #pragma unroll
        for (int nt = 0; nt < 8; nt++)
            #pragma unroll
            for (int r = 0; r < 4; r++) acc[mt][nt][r] = 0.f;

    for (int it = 0; it < NIT; ++it) {
        asm volatile("cp.async.wait_group 0;");
        __syncthreads();

        if (it + 1 < NIT) {
            __half2* sA = smem2 + ((it + 1) & 1) * STG2;
            __half2* sB = sA + 128 * GP2;
            const __half* Agt = Ag + (size_t)(it + 1) * 32;
            const __half* Bgt = Bg + (size_t)(it + 1) * 32;
            #pragma unroll
            for (int i = 0; i < 2; i++) {
                int idx = tid + i * 256;
                int row = idx >> 2, c = idx & 3;
                cp_async16(sA + row * GP2 + c * 4, Agt + (size_t)row * K + c * 8);
                cp_async16(sB + row * GP2 + c * 4, Bgt + (size_t)row * K + c * 8);
            }
            asm volatile("cp.async.commit_group;");
        }

        const __half2* sA = smem2 + (it & 1) * STG2;
        const __half2* sB = sA + 128 * GP2;

        #pragma unroll
        for (int kk2 = 0; kk2 < 16; kk2 += 8) {      // two k16 steps (half2 units)
            uint32_t a[2][4], b[8][2];
            #pragma unroll
            for (int mt = 0; mt < 2; mt++) {
                int r0 = wm * 32 + mt * 16 + fr;
                a[mt][0] = *(const uint32_t*)&sA[(r0    ) * GP2 + kk2 + fc];
                a[mt][1] = *(const uint32_t*)&sA[(r0 + 8) * GP2 + kk2 + fc];
                a[mt][2] = *(const uint32_t*)&sA[(r0    ) * GP2 + kk2 + fc + 4];
                a[mt][3] = *(const uint32_t*)&sA[(r0 + 8) * GP2 + kk2 + fc + 4];
            }
            #pragma unroll
            for (int nt = 0; nt < 8; nt++) {
                int c0 = wn * 64 + nt * 8 + fr;
                b[nt][0] = *(const uint32_t*)&sB[c0 * GP2 + kk2 + fc];
                b[nt][1] = *(const uint32_t*)&sB[c0 * GP2 + kk2 + fc + 4];
            }
            #pragma unroll
            for (int mt = 0; mt < 2; mt++)
                #pragma unroll
                for (int nt = 0; nt < 8; nt++) {
                    asm volatile(
                        "mma.sync.aligned.m16n8k16.row.col.f32.f16.f16.f32 "
                        "{%0,%1,%2,%3}, {%4,%5,%6,%7}, {%8,%9}, {%0,%1,%2,%3};"
                        : "+f"(acc[mt][nt][0]), "+f"(acc[mt][nt][1]),
                          "+f"(acc[mt][nt][2]), "+f"(acc[mt][nt][3])
                        : "r"(a[mt][0]), "r"(a[mt][1]), "r"(a[mt][2]), "r"(a[mt][3]),
                          "r"(b[nt][0]), "r"(b[nt][1]));
                }
        }
        __syncthreads();
    }

    #pragma unroll
    for (int mt = 0; mt < 2; mt++) {
        int row = bm * 128 + wm * 32 + mt * 16 + fr;
        #pragma unroll
        for (int nt = 0; nt < 8; nt++) {
            int col = bn * 128 + wn * 64 + nt * 8 + 2 * fc;
            float b0 = bias[col], b1 = bias[col + 1];
            float2 v0 = make_float2(acc[mt][nt][0] + b0, acc[mt][nt][1] + b1);
            float2 v1 = make_float2(acc[mt][nt][2] + b0, acc[mt][nt][3] + b1);
            *(float2*)(C + (size_t)row * N + col)       = v0;
            *(float2*)(C + (size_t)(row + 8) * N + col) = v1;
        }
    }
}

// ---------------- persistent GRU recurrence (fp16 tensor-core) ---------------
#define RG  128
#define CPC 8
#define RTH 256
#define SH2 516            // half2 row stride for staged h (16 rows)

__device__ __forceinline__ void grid_barrier_init()
{
    __threadfence();
    __syncthreads();
    if (threadIdx.x == 0) {
        unsigned gen;
        asm volatile("ld.acquire.gpu.global.u32 %0, [%1];"
                     : "=r"(gen) : "l"(&g_bar_gen));
        unsigned arrived = atomicAdd(&g_bar_cnt, 1u);
        if (arrived == RG - 1) {
            g_bar_cnt = 0;
            __threadfence();
            atomicAdd(&g_bar_gen, 1u);
        } else {
            for (;;) {
                unsigned cur;
                asm volatile("ld.acquire.gpu.global.u32 %0, [%1];"
                             : "=r"(cur) : "l"(&g_bar_gen));
                if (cur - gen != 0u) break;
                __nanosleep(32);
            }
        }
    }
    __syncthreads();
}

__global__ void __launch_bounds__(RTH, 1)
gru_persistent_tc(const float* __restrict__ gi, const float* __restrict__ w_hh,
                  const float* __restrict__ b_hh, float* __restrict__ hidden_out)
{
    extern __shared__ float sm[];
    __half2* sh2 = (__half2*)sm;                    // [16][SH2] staged fp16 h
    float* sp = sm + (PB * SH2 * 2) / 2;            // [8][384] warp partials (fp32)
    // (PB*SH2 half2 = PB*SH2 floats of space)

    const int tid  = threadIdx.x;
    const int g    = blockIdx.x;
    const int warp = tid >> 5;
    const int lane = tid & 31;
    const int fr   = lane >> 2;
    const int fc   = lane & 3;
    const int colbase = g * CPC;

    // ---- resident fp16 B fragments: W_hh slice (warp k-slice 128, 8 k16 steps)
    uint32_t bf[3][8][2];
    #pragma unroll
    for (int gt = 0; gt < 3; gt++) {
        const float* wrow = w_hh + ((size_t)gt * PH + colbase + fr) * PH + warp * 128;
        #pragma unroll
        for (int ks = 0; ks < 8; ks++) {
            float w0 = __ldg(wrow + ks * 16 + 2 * fc);
            float w1 = __ldg(wrow + ks * 16 + 2 * fc + 1);
            float w2 = __ldg(wrow + ks * 16 + 8 + 2 * fc);
            float w3 = __ldg(wrow + ks * 16 + 8 + 2 * fc + 1);
            __half2 p0 = __floats2half2_rn(w0, w1);
            __half2 p1 = __floats2half2_rn(w2, w3);
            bf[gt][ks][0] = *(uint32_t*)&p0;
            bf[gt][ks][1] = *(uint32_t*)&p1;
        }
    }

    // epilogue mapping: tid<128 -> (batch eb, own column ej)
    const int eb = tid >> 3;
    const int ej = colbase + (tid & 7);
    float bias_r = 0.f, bias_z = 0.f, bias_n = 0.f;
    if (tid < 128) {
        bias_r = __ldg(b_hh + 0 * PH + ej);
        bias_z = __ldg(b_hh + 1 * PH + ej);
        bias_n = __ldg(b_hh + 2 * PH + ej);
    }
    float hprev = 0.f;   // exact own-column hidden state lives in a register

    // reset flag + zero fp16 h0 slice, then one atomic init barrier
    if (tid == 0) g_flags[g] = 0u;
    {
        __half zero = __float2half(0.f);
        const int per = (PB * PH) / RG;    // 128
        for (int i = tid; i < per; i += RTH)
            g_h16[0][g * per + i] = zero;
    }
    grid_barrier_init();

    for (int t = 0; t < PS; ++t) {
        // prefetch gi (off the h dependency)
        float gir = 0.f, giz = 0.f, gin = 0.f;
        if (tid < 128) {
            const float* p = gi + ((size_t)eb * PS + t) * (3 * PH) + ej;
            gir = __ldg(p);
            giz = __ldg(p + PH);
            gin = __ldg(p + 2 * PH);
        }

        // parallel flag wait: thread i polls flag i (single acquire latency)
        if (tid < RG) {
            const unsigned* fp = &g_flags[tid];
            unsigned v;
            asm volatile("ld.acquire.gpu.global.u32 %0, [%1];"
                         : "=r"(v) : "l"(fp));
            while ((int)v < t) {
                __nanosleep(16);
                asm volatile("ld.acquire.gpu.global.u32 %0, [%1];"
                             : "=r"(v) : "l"(fp));
            }
        }
        __syncthreads();

        // stage fp16 h (32KB) into smem: 8 x 16B ldcg per thread
        {
            const uint4* h4 = (const uint4*)(&g_h16[t & 1][0]);
            #pragma unroll
            for (int i = 0; i < 8; i++) {
                int idx = tid + i * 256;            // 2048 uint4 total
                uint4 v = __ldcg(h4 + idx);
                int b = idx >> 7, r = idx & 127;
                *(uint4*)&sh2[b * SH2 + r * 4] = v;
            }
        }
        __syncthreads();

        // per-warp k-slice MMAs: 3 gates x 8 k16 steps
        float acc[3][4];
        #pragma unroll
        for (int gt = 0; gt < 3; gt++)
            #pragma unroll
            for (int r = 0; r < 4; r++) acc[gt][r] = 0.f;

        #pragma unroll
        for (int ks = 0; ks < 8; ks++) {
            int q = warp * 64 + ks * 8 + fc;        // half2 index in row
            uint32_t a0 = *(const uint32_t*)&sh2[fr * SH2 + q];
            uint32_t a1 = *(const uint32_t*)&sh2[(fr + 8) * SH2 + q];
            uint32_t a2 = *(const uint32_t*)&sh2[fr * SH2 + q + 4];
            uint32_t a3 = *(const uint32_t*)&sh2[(fr + 8) * SH2 + q + 4];
            #pragma unroll
            for (int gt = 0; gt < 3; gt++) {
                asm volatile(
                    "mma.sync.aligned.m16n8k16.row.col.f32.f16.f16.f32 "
                    "{%0,%1,%2,%3}, {%4,%5,%6,%7}, {%8,%9}, {%0,%1,%2,%3};"
                    : "+f"(acc[gt][0]), "+f"(acc[gt][1]),
                      "+f"(acc[gt][2]), "+f"(acc[gt][3])
                    : "r"(a0), "r"(a1), "r"(a2), "r"(a3),
                      "r"(bf[gt][ks][0]), "r"(bf[gt][ks][1]));
            }
        }

        // warp partials to smem
        {
            float* pw = sp + warp * 384;
            #pragma unroll
            for (int gt = 0; gt < 3; gt++) {
                pw[gt * 128 + fr * 8 + 2 * fc]           = acc[gt][0];
                pw[gt * 128 + fr * 8 + 2 * fc + 1]       = acc[gt][1];
                pw[gt * 128 + (fr + 8) * 8 + 2 * fc]     = acc[gt][2];
                pw[gt * 128 + (fr + 8) * 8 + 2 * fc + 1] = acc[gt][3];
            }
        }
        __syncthreads();

        // reduce + gates + publish (critical path first)
        float hnew = 0.f;
        __half hh;
        if (tid < 128) {
            float sr = 0.f, sz = 0.f, sn = 0.f;
            #pragma unroll
            for (int w = 0; w < 8; w++) {
                sr += sp[w * 384 +   0 + tid];
                sz += sp[w * 384 + 128 + tid];
                sn += sp[w * 384 + 256 + tid];
            }
            float r = 1.f / (1.f + __expf(-(gir + sr + bias_r)));
            float z = 1.f / (1.f + __expf(-(giz + sz + bias_z)));
            float n = tanhf(gin + r * (sn + bias_n));
            hnew = (1.f - z) * n + z * hprev;
            hh = __float2half_rn(hnew);
            g_h16[(t + 1) & 1][eb * PH + ej] = hh;
        }
        __syncthreads();
        if (tid == 0) {
            unsigned nv = (unsigned)(t + 1);
            asm volatile("st.release.gpu.global.u32 [%0], %1;"
                         :: "l"(&g_flags[g]), "r"(nv) : "memory");
        }
        // off-critical-path stores
        if (tid < 128) {
            g_rnn16[((size_t)eb * PS + t) * PH + ej] = hh;
            if (t == PS - 1) hidden_out[eb * PH + ej] = hnew;
            hprev = hnew;
        }
    }
}

// ---------------- attn = ones ------------------------------------------------
__global__ void fill_ones(float* __restrict__ p, int n)
{
    int i = blockIdx.x * blockDim.x + threadIdx.x;
    if (i < n) p[i] = 1.0f;
}

// ---------------- launch -----------------------------------------------------
extern "C" void kernel_launch(void* const* d_in, const int* in_sizes, int n_in,
                              void* d_out, int out_size)
{
    const float* x    = (const float*)d_in[0];
    // d_in[1..4] = attention params: dead (softmax over size-1 axis == 1)
    const float* w_ih = (const float*)d_in[5];
    const float* w_hh = (const float*)d_in[6];
    const float* b_ih = (const float*)d_in[7];
    const float* b_hh = (const float*)d_in[8];
    const float* fc_w = (const float*)d_in[9];
    const float* fc_b = (const float*)d_in[10];

    float* out    = (float*)d_out;                       // [B*S, I]
    float* hidden = out + (size_t)PB * PS * PI;          // [B, H]
    float* attn   = hidden + (size_t)PB * PH;            // [B*S]

    float *gi_ptr;
    __half *x16, *wih16, *fcw16, *rnn16;
    cudaGetSymbolAddress((void**)&gi_ptr, g_gi);
    cudaGetSymbolAddress((void**)&x16,    g_x16);
    cudaGetSymbolAddress((void**)&wih16,  g_wih16);
    cudaGetSymbolAddress((void**)&fcw16,  g_fcw16);
    cudaGetSymbolAddress((void**)&rnn16,  g_rnn16);

    const int M = PB * PS;   // 32768

    // 0) convert GEMM operands to fp16
    to_half<<<1184, 256>>>(x,    x16,   (PB * PS * PI) / 4);
    to_half<<<296,  256>>>(w_ih, wih16, (3 * PH * PI) / 4);
    to_half<<<296,  256>>>(fc_w, fcw16, (PI * PH) / 4);

    const size_t gsmem = 2 * (size_t)(2 * 128 * GP2) * sizeof(__half2); // 40KB
    cudaFuncSetAttribute(gemm_f16_bt_bias,
                         cudaFuncAttributeMaxDynamicSharedMemorySize, (int)gsmem);

    // 1) gi = x @ w_ih^T + b_ih   [32768, 3072] fp32
    {
        dim3 grid((3 * PH) / 128, M / 128);
        gemm_f16_bt_bias<<<grid, 256, gsmem>>>(x16, wih16, b_ih, gi_ptr,
                                               M, 3 * PH, PI);
    }

    // 2) persistent fp16 tensor-core GRU scan
    {
        size_t smem = (size_t)(PB * SH2) * sizeof(__half2)
                    + (size_t)(8 * 384) * sizeof(float);
        cudaFuncSetAttribute(gru_persistent_tc,
                             cudaFuncAttributeMaxDynamicSharedMemorySize,
                             (int)smem);
        gru_persistent_tc<<<RG, RTH, smem>>>(gi_ptr, w_hh, b_hh, hidden);
    }

    // 3) output = rnn16 @ fcw16^T + fc_b   [32768, 1024]
    {
        dim3 grid(PI / 128, M / 128);
        gemm_f16_bt_bias<<<grid, 256, gsmem>>>(rnn16, fcw16, fc_b, out,
                                               M, PI, PH);
    }

    // 4) attn = 1.0
    {
        int n = PB * PS;
        fill_ones<<<(n + 255) / 256, 256>>>(attn, n);
    }
}

// round 6
// speedup vs baseline: 2.6738x; 1.2561x over previous
#include <cuda_runtime.h>
#include <cuda_fp16.h>
#include <cstdint>
#include <cstddef>

// Problem constants
#define PB 16
#define PS 2048
#define PI 1024
#define PH 1024

// ---------------- scratch (device globals; no allocs allowed) ----------------
__device__ float  g_gi[(size_t)PB * PS * (3 * PH)];   // [B*S, 3H] fp32
__device__ __half g_x16[(size_t)PB * PS * PI];
__device__ __half g_wih16[(size_t)(3 * PH) * PI];
__device__ __half g_h16[2][PB * PH];                  // ping-pong hidden (fp16)
__device__ unsigned g_cnt;                            // step arrival counter
__device__ unsigned g_bar_cnt;
__device__ unsigned g_bar_gen;

// ---------------- fp32 -> fp16 prepass ---------------------------------------
__global__ void __launch_bounds__(256)
to_half(const float* __restrict__ src, __half* __restrict__ dst, int n4)
{
    int i = blockIdx.x * blockDim.x + threadIdx.x;
    int stride = gridDim.x * blockDim.x;
    for (; i < n4; i += stride) {
        float4 v = ((const float4*)src)[i];
        __half2 h0 = __floats2half2_rn(v.x, v.y);
        __half2 h1 = __floats2half2_rn(v.z, v.w);
        ((__half2*)dst)[2 * i]     = h0;
        ((__half2*)dst)[2 * i + 1] = h1;
    }
}

// ---------------- fp16 tensor-core GEMM: C = A[M,K] @ B[N,K]^T + bias --------
#define GP2 20

__device__ __forceinline__ void cp_async16(void* smem, const void* gmem)
{
    uint32_t s = (uint32_t)__cvta_generic_to_shared(smem);
    asm volatile("cp.async.cg.shared.global [%0], [%1], 16;" :: "r"(s), "l"(gmem));
}

__global__ void __launch_bounds__(256, 2)
gemm_f16_bt_bias(const __half* __restrict__ A, const __half* __restrict__ B,
                 const float* __restrict__ bias, float* __restrict__ C,
                 int M, int N, int K)
{
    extern __shared__ __half2 smem2[];
    const int STG2 = 2 * 128 * GP2;

    const int tid  = threadIdx.x;
    const int wid  = tid >> 5;
    const int lane = tid & 31;
    const int wm   = wid >> 1;
    const int wn   = wid & 1;
    const int fr   = lane >> 2;
    const int fc   = lane & 3;

    const int bm = blockIdx.y, bn = blockIdx.x;
    const __half* Ag = A + (size_t)(bm * 128) * K;
    const __half* Bg = B + (size_t)(bn * 128) * K;

    const int NIT = K / 32;

    {
        __half2* sA = smem2;
        __half2* sB = smem2 + 128 * GP2;
        #pragma unroll
        for (int i = 0; i < 2; i++) {
            int idx = tid + i * 256;
            int row = idx >> 2, c = idx & 3;
            cp_async16(sA + row * GP2 + c * 4, Ag + (size_t)row * K + c * 8);
            cp_async16(sB + row * GP2 + c * 4, Bg + (size_t)row * K + c * 8);
        }
        asm volatile("cp.async.commit_group;");
    }

    float acc[2][8][4];
    #pragma unroll
    for (int mt = 0; mt < 2; mt++)
        #pragma unroll
        for (int nt = 0; nt < 8; nt++)
            #pragma unroll
            for (int r = 0; r < 4; r++) acc[mt][nt][r] = 0.f;

    for (int it = 0; it < NIT; ++it) {
        asm volatile("cp.async.wait_group 0;");
        __syncthreads();

        if (it + 1 < NIT) {
            __half2* sA = smem2 + ((it + 1) & 1) * STG2;
            __half2* sB = sA + 128 * GP2;
            const __half* Agt = Ag + (size_t)(it + 1) * 32;
            const __half* Bgt = Bg + (size_t)(it + 1) * 32;
            #pragma unroll
            for (int i = 0; i < 2; i++) {
                int idx = tid + i * 256;
                int row = idx >> 2, c = idx & 3;
                cp_async16(sA + row * GP2 + c * 4, Agt + (size_t)row * K + c * 8);
                cp_async16(sB + row * GP2 + c * 4, Bgt + (size_t)row * K + c * 8);
            }
            asm volatile("cp.async.commit_group;");
        }

        const __half2* sA = smem2 + (it & 1) * STG2;
        const __half2* sB = sA + 128 * GP2;

        #pragma unroll
        for (int kk2 = 0; kk2 < 16; kk2 += 8) {
            uint32_t a[2][4], b[8][2];
            #pragma unroll
            for (int mt = 0; mt < 2; mt++) {
                int r0 = wm * 32 + mt * 16 + fr;
                a[mt][0] = *(const uint32_t*)&sA[(r0    ) * GP2 + kk2 + fc];
                a[mt][1] = *(const uint32_t*)&sA[(r0 + 8) * GP2 + kk2 + fc];
                a[mt][2] = *(const uint32_t*)&sA[(r0    ) * GP2 + kk2 + fc + 4];
                a[mt][3] = *(const uint32_t*)&sA[(r0 + 8) * GP2 + kk2 + fc + 4];
            }
            #pragma unroll
            for (int nt = 0; nt < 8; nt++) {
                int c0 = wn * 64 + nt * 8 + fr;
                b[nt][0] = *(const uint32_t*)&sB[c0 * GP2 + kk2 + fc];
                b[nt][1] = *(const uint32_t*)&sB[c0 * GP2 + kk2 + fc + 4];
            }
            #pragma unroll
            for (int mt = 0; mt < 2; mt++)
                #pragma unroll
                for (int nt = 0; nt < 8; nt++) {
                    asm volatile(
                        "mma.sync.aligned.m16n8k16.row.col.f32.f16.f16.f32 "
                        "{%0,%1,%2,%3}, {%4,%5,%6,%7}, {%8,%9}, {%0,%1,%2,%3};"
                        : "+f"(acc[mt][nt][0]), "+f"(acc[mt][nt][1]),
                          "+f"(acc[mt][nt][2]), "+f"(acc[mt][nt][3])
                        : "r"(a[mt][0]), "r"(a[mt][1]), "r"(a[mt][2]), "r"(a[mt][3]),
                          "r"(b[nt][0]), "r"(b[nt][1]));
                }
        }
        __syncthreads();
    }

    #pragma unroll
    for (int mt = 0; mt < 2; mt++) {
        int row = bm * 128 + wm * 32 + mt * 16 + fr;
        #pragma unroll
        for (int nt = 0; nt < 8; nt++) {
            int col = bn * 128 + wn * 64 + nt * 8 + 2 * fc;
            float b0 = bias[col], b1 = bias[col + 1];
            float2 v0 = make_float2(acc[mt][nt][0] + b0, acc[mt][nt][1] + b1);
            float2 v1 = make_float2(acc[mt][nt][2] + b0, acc[mt][nt][3] + b1);
            *(float2*)(C + (size_t)row * N + col)       = v0;
            *(float2*)(C + (size_t)(row + 8) * N + col) = v1;
        }
    }
}

// ---------------- persistent GRU recurrence + fused fc -----------------------
#define RG  128
#define CPC 8
#define RTH 256

__device__ __forceinline__ void grid_barrier_init()
{
    __threadfence();
    __syncthreads();
    if (threadIdx.x == 0) {
        unsigned gen;
        asm volatile("ld.acquire.gpu.global.u32 %0, [%1];"
                     : "=r"(gen) : "l"(&g_bar_gen));
        unsigned arrived = atomicAdd(&g_bar_cnt, 1u);
        if (arrived == RG - 1) {
            g_bar_cnt = 0;
            __threadfence();
            atomicAdd(&g_bar_gen, 1u);
        } else {
            for (;;) {
                unsigned cur;
                asm volatile("ld.acquire.gpu.global.u32 %0, [%1];"
                             : "=r"(cur) : "l"(&g_bar_gen));
                if (cur - gen != 0u) break;
                __nanosleep(32);
            }
        }
    }
    __syncthreads();
}

__global__ void __launch_bounds__(RTH, 1)
gru_persistent_tc(const float* __restrict__ gi, const float* __restrict__ w_hh,
                  const float* __restrict__ b_hh,
                  const float* __restrict__ fc_w, const float* __restrict__ fc_b,
                  float* __restrict__ out, float* __restrict__ hidden_out)
{
    __shared__ float sp[8 * 512];        // [warp][4 chains][128] partials

    const int tid  = threadIdx.x;
    const int g    = blockIdx.x;
    const int warp = tid >> 5;
    const int lane = tid & 31;
    const int fr   = lane >> 2;
    const int fc   = lane & 3;
    const int colbase = g * CPC;

    // ---- resident fp16 B fragments: W_hh (3 gates) + fc_w (1 tile) ----
    uint32_t bf[3][8][2];
    #pragma unroll
    for (int gt = 0; gt < 3; gt++) {
        const float* wrow = w_hh + ((size_t)gt * PH + colbase + fr) * PH + warp * 128;
        #pragma unroll
        for (int ks = 0; ks < 8; ks++) {
            __half2 p0 = __floats2half2_rn(__ldg(wrow + ks * 16 + 2 * fc),
                                           __ldg(wrow + ks * 16 + 2 * fc + 1));
            __half2 p1 = __floats2half2_rn(__ldg(wrow + ks * 16 + 8 + 2 * fc),
                                           __ldg(wrow + ks * 16 + 8 + 2 * fc + 1));
            bf[gt][ks][0] = *(uint32_t*)&p0;
            bf[gt][ks][1] = *(uint32_t*)&p1;
        }
    }
    uint32_t ff[8][2];
    {
        const float* frow = fc_w + ((size_t)(colbase + fr)) * PH + warp * 128;
        #pragma unroll
        for (int ks = 0; ks < 8; ks++) {
            __half2 p0 = __floats2half2_rn(__ldg(frow + ks * 16 + 2 * fc),
                                           __ldg(frow + ks * 16 + 2 * fc + 1));
            __half2 p1 = __floats2half2_rn(__ldg(frow + ks * 16 + 8 + 2 * fc),
                                           __ldg(frow + ks * 16 + 8 + 2 * fc + 1));
            ff[ks][0] = *(uint32_t*)&p0;
            ff[ks][1] = *(uint32_t*)&p1;
        }
    }

    // epilogue mapping: tid<128 -> (batch eb, own column ej)
    const int eb = tid >> 3;
    const int ej = colbase + (tid & 7);
    float bias_r = 0.f, bias_z = 0.f, bias_n = 0.f, bias_fc = 0.f;
    if (tid < 128) {
        bias_r  = __ldg(b_hh + 0 * PH + ej);
        bias_z  = __ldg(b_hh + 1 * PH + ej);
        bias_n  = __ldg(b_hh + 2 * PH + ej);
        bias_fc = __ldg(fc_b + ej);
    }
    float hprev = 0.f;

    // reset counter + zero fp16 h0 slice, then one init barrier
    if (tid == 0) g_cnt = 0u;
    {
        __half zero = __float2half(0.f);
        const int per = (PB * PH) / RG;    // 128
        for (int i = tid; i < per; i += RTH)
            g_h16[0][g * per + i] = zero;
    }
    grid_barrier_init();

    for (int t = 0; t < PS; ++t) {
        // prefetch gi (independent of h availability)
        float gir = 0.f, giz = 0.f, gin = 0.f;
        if (tid < 128) {
            const float* p = gi + ((size_t)eb * PS + t) * (3 * PH) + ej;
            gir = __ldg(p);
            giz = __ldg(p + PH);
            gin = __ldg(p + 2 * PH);
        }

        // single-counter wait: all CTAs arrived for step t
        if (tid == 0) {
            const unsigned target = (unsigned)RG * (unsigned)t;
            unsigned v;
            do {
                asm volatile("ld.acquire.gpu.global.u32 %0, [%1];"
                             : "=r"(v) : "l"(&g_cnt));
            } while (v < target);
        }
        __syncthreads();

        // direct A-fragments from global h (no smem staging)
        const uint32_t* hb = (const uint32_t*)(&g_h16[t & 1][0]);
        uint32_t a0[8], a1[8], a2[8], a3[8];
        #pragma unroll
        for (int ks = 0; ks < 8; ks++) {
            int q = warp * 64 + ks * 8 + fc;          // u32 index within row
            a0[ks] = __ldcg(hb + (size_t)fr * 512 + q);
            a1[ks] = __ldcg(hb + (size_t)(fr + 8) * 512 + q);
            a2[ks] = __ldcg(hb + (size_t)fr * 512 + q + 4);
            a3[ks] = __ldcg(hb + (size_t)(fr + 8) * 512 + q + 4);
        }

        // 4 chains: r, z, n gates + fc (for timestep t-1)
        float acc[4][4];
        #pragma unroll
        for (int c = 0; c < 4; c++)
            #pragma unroll
            for (int r = 0; r < 4; r++) acc[c][r] = 0.f;

        #pragma unroll
        for (int ks = 0; ks < 8; ks++) {
            #pragma unroll
            for (int gt = 0; gt < 3; gt++) {
                asm volatile(
                    "mma.sync.aligned.m16n8k16.row.col.f32.f16.f16.f32 "
                    "{%0,%1,%2,%3}, {%4,%5,%6,%7}, {%8,%9}, {%0,%1,%2,%3};"
                    : "+f"(acc[gt][0]), "+f"(acc[gt][1]),
                      "+f"(acc[gt][2]), "+f"(acc[gt][3])
                    : "r"(a0[ks]), "r"(a1[ks]), "r"(a2[ks]), "r"(a3[ks]),
                      "r"(bf[gt][ks][0]), "r"(bf[gt][ks][1]));
            }
            asm volatile(
                "mma.sync.aligned.m16n8k16.row.col.f32.f16.f16.f32 "
                "{%0,%1,%2,%3}, {%4,%5,%6,%7}, {%8,%9}, {%0,%1,%2,%3};"
                : "+f"(acc[3][0]), "+f"(acc[3][1]),
                  "+f"(acc[3][2]), "+f"(acc[3][3])
                : "r"(a0[ks]), "r"(a1[ks]), "r"(a2[ks]), "r"(a3[ks]),
                  "r"(ff[ks][0]), "r"(ff[ks][1]));
        }

        // warp partials to smem (all 4 chains)
        {
            float* pw = sp + warp * 512;
            #pragma unroll
            for (int c = 0; c < 4; c++) {
                pw[c * 128 + fr * 8 + 2 * fc]           = acc[c][0];
                pw[c * 128 + fr * 8 + 2 * fc + 1]       = acc[c][1];
                pw[c * 128 + (fr + 8) * 8 + 2 * fc]     = acc[c][2];
                pw[c * 128 + (fr + 8) * 8 + 2 * fc + 1] = acc[c][3];
            }
        }
        __syncthreads();

        // critical path: reduce gates, update h, publish
        if (tid < 128) {
            float sr = 0.f, sz = 0.f, sn = 0.f;
            #pragma unroll
            for (int w = 0; w < 8; w++) {
                sr += sp[w * 512 +   0 + tid];
                sz += sp[w * 512 + 128 + tid];
                sn += sp[w * 512 + 256 + tid];
            }
            float r = 1.f / (1.f + __expf(-(gir + sr + bias_r)));
            float z = 1.f / (1.f + __expf(-(giz + sz + bias_z)));
            float n = tanhf(gin + r * (sn + bias_n));
            float hnew = (1.f - z) * n + z * hprev;
            __half hh = __float2half_rn(hnew);
            g_h16[(t + 1) & 1][eb * PH + ej] = hh;
            hprev = hnew;
            if (t == PS - 1) hidden_out[eb * PH + ej] = hnew;
        }
        __syncthreads();
        if (tid == 0) {
            asm volatile("red.release.gpu.global.add.u32 [%0], %1;"
                         :: "l"(&g_cnt), "r"(1u) : "memory");
        }

        // off critical path: fc output for timestep t-1
        if (t > 0 && tid < 128) {
            float so = 0.f;
            #pragma unroll
            for (int w = 0; w < 8; w++) so += sp[w * 512 + 384 + tid];
            out[((size_t)eb * PS + (t - 1)) * PI + ej] = so + bias_fc;
        }
    }

    // ---- tail: fc for the final timestep (uses h(PS) in buf[0]) ----
    if (tid == 0) {
        const unsigned target = (unsigned)RG * (unsigned)PS;
        unsigned v;
        do {
            asm volatile("ld.acquire.gpu.global.u32 %0, [%1];"
                         : "=r"(v) : "l"(&g_cnt));
        } while (v < target);
    }
    __syncthreads();
    {
        const uint32_t* hb = (const uint32_t*)(&g_h16[PS & 1][0]);
        float acc[4] = {0.f, 0.f, 0.f, 0.f};
        #pragma unroll
        for (int ks = 0; ks < 8; ks++) {
            int q = warp * 64 + ks * 8 + fc;
            uint32_t a0 = __ldcg(hb + (size_t)fr * 512 + q);
            uint32_t a1 = __ldcg(hb + (size_t)(fr + 8) * 512 + q);
            uint32_t a2 = __ldcg(hb + (size_t)fr * 512 + q + 4);
            uint32_t a3 = __ldcg(hb + (size_t)(fr + 8) * 512 + q + 4);
            asm volatile(
                "mma.sync.aligned.m16n8k16.row.col.f32.f16.f16.f32 "
                "{%0,%1,%2,%3}, {%4,%5,%6,%7}, {%8,%9}, {%0,%1,%2,%3};"
                : "+f"(acc[0]), "+f"(acc[1]), "+f"(acc[2]), "+f"(acc[3])
                : "r"(a0), "r"(a1), "r"(a2), "r"(a3),
                  "r"(ff[ks][0]), "r"(ff[ks][1]));
        }
        float* pw = sp + warp * 512;
        pw[384 + fr * 8 + 2 * fc]           = acc[0];
        pw[384 + fr * 8 + 2 * fc + 1]       = acc[1];
        pw[384 + (fr + 8) * 8 + 2 * fc]     = acc[2];
        pw[384 + (fr + 8) * 8 + 2 * fc + 1] = acc[3];
    }
    __syncthreads();
    if (tid < 128) {
        float so = 0.f;
        #pragma unroll
        for (int w = 0; w < 8; w++) so += sp[w * 512 + 384 + tid];
        out[((size_t)eb * PS + (PS - 1)) * PI + ej] = so + bias_fc;
    }
}

// ---------------- attn = ones ------------------------------------------------
__global__ void fill_ones(float* __restrict__ p, int n)
{
    int i = blockIdx.x * blockDim.x + threadIdx.x;
    if (i < n) p[i] = 1.0f;
}

// ---------------- launch -----------------------------------------------------
extern "C" void kernel_launch(void* const* d_in, const int* in_sizes, int n_in,
                              void* d_out, int out_size)
{
    const float* x    = (const float*)d_in[0];
    // d_in[1..4] = attention params: dead (softmax over size-1 axis == 1)
    const float* w_ih = (const float*)d_in[5];
    const float* w_hh = (const float*)d_in[6];
    const float* b_ih = (const float*)d_in[7];
    const float* b_hh = (const float*)d_in[8];
    const float* fc_w = (const float*)d_in[9];
    const float* fc_b = (const float*)d_in[10];

    float* out    = (float*)d_out;                       // [B*S, I]
    float* hidden = out + (size_t)PB * PS * PI;          // [B, H]
    float* attn   = hidden + (size_t)PB * PH;            // [B*S]

    float *gi_ptr;
    __half *x16, *wih16;
    cudaGetSymbolAddress((void**)&gi_ptr, g_gi);
    cudaGetSymbolAddress((void**)&x16,    g_x16);
    cudaGetSymbolAddress((void**)&wih16,  g_wih16);

    const int M = PB * PS;   // 32768

    // 0) convert gi-GEMM operands to fp16
    to_half<<<1184, 256>>>(x,    x16,   (PB * PS * PI) / 4);
    to_half<<<296,  256>>>(w_ih, wih16, (3 * PH * PI) / 4);

    const size_t gsmem = 2 * (size_t)(2 * 128 * GP2) * sizeof(__half2); // 40KB
    cudaFuncSetAttribute(gemm_f16_bt_bias,
                         cudaFuncAttributeMaxDynamicSharedMemorySize, (int)gsmem);

    // 1) gi = x @ w_ih^T + b_ih   [32768, 3072] fp32
    {
        dim3 grid((3 * PH) / 128, M / 128);
        gemm_f16_bt_bias<<<grid, 256, gsmem>>>(x16, wih16, b_ih, gi_ptr,
                                               M, 3 * PH, PI);
    }

    // 2) persistent GRU scan + fused fc output
    gru_persistent_tc<<<RG, RTH>>>(gi_ptr, w_hh, b_hh, fc_w, fc_b, out, hidden);

    // 3) attn = 1.0
    {
        int n = PB * PS;
        fill_ones<<<(n + 255) / 256, 256>>>(attn, n);
    }
}

// round 13
// speedup vs baseline: 2.9592x; 1.1067x over previous
#include <cuda_runtime.h>
#include <cuda_fp16.h>
#include <cstdint>
#include <cstddef>

// Problem constants
#define PB 16
#define PS 2048
#define PI 1024
#define PH 1024

// ---------------- scratch (device globals; no allocs allowed) ----------------
__device__ float  g_gi[(size_t)PB * PS * (3 * PH)];   // [B*S, 3H] fp32
__device__ __half g_x16[(size_t)PB * PS * PI];
__device__ __half g_wih16[(size_t)(3 * PH) * PI];
__device__ __half g_h16[2][PB * PH];                  // ping-pong hidden (fp16)
__device__ unsigned g_cnt;                            // step arrival counter
__device__ unsigned g_bar_cnt;
__device__ unsigned g_bar_gen;

// ---------------- fast activations (approx exp/rcp; abs err ~1e-6) ----------
__device__ __forceinline__ float fast_sigmoid(float x)
{
    float e = __expf(-x);
    return __fdividef(1.f, 1.f + e);
}
__device__ __forceinline__ float fast_tanh(float x)
{
    float e = __expf(2.f * x);          // x<<0: e->0 -> -1; x>>0: e->inf -> 1
    return 1.f - __fdividef(2.f, 1.f + e);
}

// ---------------- fp32 -> fp16 prepass ---------------------------------------
__global__ void __launch_bounds__(256)
to_half(const float* __restrict__ src, __half* __restrict__ dst, int n4)
{
    int i = blockIdx.x * blockDim.x + threadIdx.x;
    int stride = gridDim.x * blockDim.x;
    for (; i < n4; i += stride) {
        float4 v = ((const float4*)src)[i];
        __half2 h0 = __floats2half2_rn(v.x, v.y);
        __half2 h1 = __floats2half2_rn(v.z, v.w);
        ((__half2*)dst)[2 * i]     = h0;
        ((__half2*)dst)[2 * i + 1] = h1;
    }
}

// ---------------- fp16 tensor-core GEMM: C = A[M,K] @ B[N,K]^T + bias --------
// (R6-proven scalar-LDS fragment loads; ldmatrix variant withheld pending
//  container-failure isolation)
#define GP2 20

__device__ __forceinline__ void cp_async16(void* smem, const void* gmem)
{
    uint32_t s = (uint32_t)__cvta_generic_to_shared(smem);
    asm volatile("cp.async.cg.shared.global [%0], [%1], 16;" :: "r"(s), "l"(gmem));
}

__global__ void __launch_bounds__(256, 2)
gemm_f16_bt_bias(const __half* __restrict__ A, const __half* __restrict__ B,
                 const float* __restrict__ bias, float* __restrict__ C,
                 int M, int N, int K)
{
    extern __shared__ __half2 smem2[];
    const int STG2 = 2 * 128 * GP2;

    const int tid  = threadIdx.x;
    const int wid  = tid >> 5;
    const int lane = tid & 31;
    const int wm   = wid >> 1;
    const int wn   = wid & 1;
    const int fr   = lane >> 2;
    const int fc   = lane & 3;

    const int bm = blockIdx.y, bn = blockIdx.x;
    const __half* Ag = A + (size_t)(bm * 128) * K;
    const __half* Bg = B + (size_t)(bn * 128) * K;

    const int NIT = K / 32;

    {
        __half2* sA = smem2;
        __half2* sB = smem2 + 128 * GP2;
        #pragma unroll
        for (int i = 0; i < 2; i++) {
            int idx = tid + i * 256;
            int row = idx >> 2, c = idx & 3;
            cp_async16(sA + row * GP2 + c * 4, Ag + (size_t)row * K + c * 8);
            cp_async16(sB + row * GP2 + c * 4, Bg + (size_t)row * K + c * 8);
        }
        asm volatile("cp.async.commit_group;");
    }

    float acc[2][8][4];
    #pragma unroll
    for (int mt = 0; mt < 2; mt++)
        #pragma unroll
        for (int nt = 0; nt < 8; nt++)
            #pragma unroll
            for (int r = 0; r < 4; r++) acc[mt][nt][r] = 0.f;

    for (int it = 0; it < NIT; ++it) {
        asm volatile("cp.async.wait_group 0;");
        __syncthreads();

        if (it + 1 < NIT) {
            __half2* sA = smem2 + ((it + 1) & 1) * STG2;
            __half2* sB = sA + 128 * GP2;
            const __half* Agt = Ag + (size_t)(it + 1) * 32;
            const __half* Bgt = Bg + (size_t)(it + 1) * 32;
            #pragma unroll
            for (int i = 0; i < 2; i++) {
                int idx = tid + i * 256;
                int row = idx >> 2, c = idx & 3;
                cp_async16(sA + row * GP2 + c * 4, Agt + (size_t)row * K + c * 8);
                cp_async16(sB + row * GP2 + c * 4, Bgt + (size_t)row * K + c * 8);
            }
            asm volatile("cp.async.commit_group;");
        }

        const __half2* sA = smem2 + (it & 1) * STG2;
        const __half2* sB = sA + 128 * GP2;

        #pragma unroll
        for (int kk2 = 0; kk2 < 16; kk2 += 8) {
            uint32_t a[2][4], b[8][2];
            #pragma unroll
            for (int mt = 0; mt < 2; mt++) {
                int r0 = wm * 32 + mt * 16 + fr;
                a[mt][0] = *(const uint32_t*)&sA[(r0    ) * GP2 + kk2 + fc];
                a[mt][1] = *(const uint32_t*)&sA[(r0 + 8) * GP2 + kk2 + fc];
                a[mt][2] = *(const uint32_t*)&sA[(r0    ) * GP2 + kk2 + fc + 4];
                a[mt][3] = *(const uint32_t*)&sA[(r0 + 8) * GP2 + kk2 + fc + 4];
            }
            #pragma unroll
            for (int nt = 0; nt < 8; nt++) {
                int c0 = wn * 64 + nt * 8 + fr;
                b[nt][0] = *(const uint32_t*)&sB[c0 * GP2 + kk2 + fc];
                b[nt][1] = *(const uint32_t*)&sB[c0 * GP2 + kk2 + fc + 4];
            }
            #pragma unroll
            for (int mt = 0; mt < 2; mt++)
                #pragma unroll
                for (int nt = 0; nt < 8; nt++) {
                    asm volatile(
                        "mma.sync.aligned.m16n8k16.row.col.f32.f16.f16.f32 "
                        "{%0,%1,%2,%3}, {%4,%5,%6,%7}, {%8,%9}, {%0,%1,%2,%3};"
                        : "+f"(acc[mt][nt][0]), "+f"(acc[mt][nt][1]),
                          "+f"(acc[mt][nt][2]), "+f"(acc[mt][nt][3])
                        : "r"(a[mt][0]), "r"(a[mt][1]), "r"(a[mt][2]), "r"(a[mt][3]),
                          "r"(b[nt][0]), "r"(b[nt][1]));
                }
        }
        __syncthreads();
    }

    #pragma unroll
    for (int mt = 0; mt < 2; mt++) {
        int row = bm * 128 + wm * 32 + mt * 16 + fr;
        #pragma unroll
        for (int nt = 0; nt < 8; nt++) {
            int col = bn * 128 + wn * 64 + nt * 8 + 2 * fc;
            float b0 = bias[col], b1 = bias[col + 1];
            float2 v0 = make_float2(acc[mt][nt][0] + b0, acc[mt][nt][1] + b1);
            float2 v1 = make_float2(acc[mt][nt][2] + b0, acc[mt][nt][3] + b1);
            *(float2*)(C + (size_t)row * N + col)       = v0;
            *(float2*)(C + (size_t)(row + 8) * N + col) = v1;
        }
    }
}

// ---------------- persistent GRU recurrence + fused fc -----------------------
#define RG  128
#define CPC 8
#define RTH 256

__device__ __forceinline__ void grid_barrier_init()
{
    __threadfence();
    __syncthreads();
    if (threadIdx.x == 0) {
        unsigned gen;
        asm volatile("ld.acquire.gpu.global.u32 %0, [%1];"
                     : "=r"(gen) : "l"(&g_bar_gen));
        unsigned arrived = atomicAdd(&g_bar_cnt, 1u);
        if (arrived == RG - 1) {
            g_bar_cnt = 0;
            __threadfence();
            atomicAdd(&g_bar_gen, 1u);
        } else {
            for (;;) {
                unsigned cur;
                asm volatile("ld.acquire.gpu.global.u32 %0, [%1];"
                             : "=r"(cur) : "l"(&g_bar_gen));
                if (cur - gen != 0u) break;
                __nanosleep(32);
            }
        }
    }
    __syncthreads();
}

__global__ void __launch_bounds__(RTH, 1)
gru_persistent_tc(const float* __restrict__ gi, const float* __restrict__ w_hh,
                  const float* __restrict__ b_hh,
                  const float* __restrict__ fc_w, const float* __restrict__ fc_b,
                  float* __restrict__ out, float* __restrict__ hidden_out)
{
    __shared__ float sp[8 * 512];        // [warp][4 chains][128] partials

    const int tid  = threadIdx.x;
    const int g    = blockIdx.x;
    const int warp = tid >> 5;
    const int lane = tid & 31;
    const int fr   = lane >> 2;
    const int fc   = lane & 3;
    const int colbase = g * CPC;

    // ---- resident fp16 B fragments: W_hh (3 gates) + fc_w (1 tile) ----
    uint32_t bf[3][8][2];
    #pragma unroll
    for (int gt = 0; gt < 3; gt++) {
        const float* wrow = w_hh + ((size_t)gt * PH + colbase + fr) * PH + warp * 128;
        #pragma unroll
        for (int ks = 0; ks < 8; ks++) {
            __half2 p0 = __floats2half2_rn(__ldg(wrow + ks * 16 + 2 * fc),
                                           __ldg(wrow + ks * 16 + 2 * fc + 1));
            __half2 p1 = __floats2half2_rn(__ldg(wrow + ks * 16 + 8 + 2 * fc),
                                           __ldg(wrow + ks * 16 + 8 + 2 * fc + 1));
            bf[gt][ks][0] = *(uint32_t*)&p0;
            bf[gt][ks][1] = *(uint32_t*)&p1;
        }
    }
    uint32_t ff[8][2];
    {
        const float* frow = fc_w + ((size_t)(colbase + fr)) * PH + warp * 128;
        #pragma unroll
        for (int ks = 0; ks < 8; ks++) {
            __half2 p0 = __floats2half2_rn(__ldg(frow + ks * 16 + 2 * fc),
                                           __ldg(frow + ks * 16 + 2 * fc + 1));
            __half2 p1 = __floats2half2_rn(__ldg(frow + ks * 16 + 8 + 2 * fc),
                                           __ldg(frow + ks * 16 + 8 + 2 * fc + 1));
            ff[ks][0] = *(uint32_t*)&p0;
            ff[ks][1] = *(uint32_t*)&p1;
        }
    }

    // epilogue mapping: tid<128 -> (batch eb, own column ej)
    const int eb = tid >> 3;
    const int ej = colbase + (tid & 7);
    float bias_r = 0.f, bias_z = 0.f, bias_n = 0.f, bias_fc = 0.f;
    if (tid < 128) {
        bias_r  = __ldg(b_hh + 0 * PH + ej);
        bias_z  = __ldg(b_hh + 1 * PH + ej);
        bias_n  = __ldg(b_hh + 2 * PH + ej);
        bias_fc = __ldg(fc_b + ej);
    }
    float hprev = 0.f;

    // reset counter + zero fp16 h0 slice, then one init barrier
    if (tid == 0) g_cnt = 0u;
    {
        __half zero = __float2half(0.f);
        const int per = (PB * PH) / RG;    // 128
        for (int i = tid; i < per; i += RTH)
            g_h16[0][g * per + i] = zero;
    }
    grid_barrier_init();

    for (int t = 0; t < PS; ++t) {
        // prefetch gi (independent of h availability)
        float gir = 0.f, giz = 0.f, gin = 0.f;
        if (tid < 128) {
            const float* p = gi + ((size_t)eb * PS + t) * (3 * PH) + ej;
            gir = __ldg(p);
            giz = __ldg(p + PH);
            gin = __ldg(p + 2 * PH);
        }

        // single-counter wait: all CTAs arrived for step t
        if (tid == 0) {
            const unsigned target = (unsigned)RG * (unsigned)t;
            unsigned v;
            do {
                asm volatile("ld.acquire.gpu.global.u32 %0, [%1];"
                             : "=r"(v) : "l"(&g_cnt));
            } while (v < target);
        }
        __syncthreads();

        // direct A-fragments from global h (no smem staging)
        const uint32_t* hb = (const uint32_t*)(&g_h16[t & 1][0]);
        uint32_t a0[8], a1[8], a2[8], a3[8];
        #pragma unroll
        for (int ks = 0; ks < 8; ks++) {
            int q = warp * 64 + ks * 8 + fc;
            a0[ks] = __ldcg(hb + (size_t)fr * 512 + q);
            a1[ks] = __ldcg(hb + (size_t)(fr + 8) * 512 + q);
            a2[ks] = __ldcg(hb + (size_t)fr * 512 + q + 4);
            a3[ks] = __ldcg(hb + (size_t)(fr + 8) * 512 + q + 4);
        }

        // critical-path MMAs: 3 gates only
        float acc[3][4];
        #pragma unroll
        for (int c = 0; c < 3; c++)
            #pragma unroll
            for (int r = 0; r < 4; r++) acc[c][r] = 0.f;
        #pragma unroll
        for (int ks = 0; ks < 8; ks++) {
            #pragma unroll
            for (int gt = 0; gt < 3; gt++) {
                asm volatile(
                    "mma.sync.aligned.m16n8k16.row.col.f32.f16.f16.f32 "
                    "{%0,%1,%2,%3}, {%4,%5,%6,%7}, {%8,%9}, {%0,%1,%2,%3};"
                    : "+f"(acc[gt][0]), "+f"(acc[gt][1]),
                      "+f"(acc[gt][2]), "+f"(acc[gt][3])
                    : "r"(a0[ks]), "r"(a1[ks]), "r"(a2[ks]), "r"(a3[ks]),
                      "r"(bf[gt][ks][0]), "r"(bf[gt][ks][1]));
            }
        }

        // gate partials to smem
        {
            float* pw = sp + warp * 512;
            #pragma unroll
            for (int c = 0; c < 3; c++) {
                pw[c * 128 + fr * 8 + 2 * fc]           = acc[c][0];
                pw[c * 128 + fr * 8 + 2 * fc + 1]       = acc[c][1];
                pw[c * 128 + (fr + 8) * 8 + 2 * fc]     = acc[c][2];
                pw[c * 128 + (fr + 8) * 8 + 2 * fc + 1] = acc[c][3];
            }
        }

        // fc MMAs for timestep t-1: issue now, epilogue later (off crit path)
        float fca[4] = {0.f, 0.f, 0.f, 0.f};
        #pragma unroll
        for (int ks = 0; ks < 8; ks++) {
            asm volatile(
                "mma.sync.aligned.m16n8k16.row.col.f32.f16.f16.f32 "
                "{%0,%1,%2,%3}, {%4,%5,%6,%7}, {%8,%9}, {%0,%1,%2,%3};"
                : "+f"(fca[0]), "+f"(fca[1]), "+f"(fca[2]), "+f"(fca[3])
                : "r"(a0[ks]), "r"(a1[ks]), "r"(a2[ks]), "r"(a3[ks]),
                  "r"(ff[ks][0]), "r"(ff[ks][1]));
        }
        __syncthreads();

        // critical path: reduce gates, update h, publish
        if (tid < 128) {
            float sr = 0.f, sz = 0.f, sn = 0.f;
            #pragma unroll
            for (int w = 0; w < 8; w++) {
                sr += sp[w * 512 +   0 + tid];
                sz += sp[w * 512 + 128 + tid];
                sn += sp[w * 512 + 256 + tid];
            }
            float r = fast_sigmoid(gir + sr + bias_r);
            float z = fast_sigmoid(giz + sz + bias_z);
            float n = fast_tanh(gin + r * (sn + bias_n));
            float hnew = (1.f - z) * n + z * hprev;
            __half hh = __float2half_rn(hnew);
            g_h16[(t + 1) & 1][eb * PH + ej] = hh;
            hprev = hnew;
            if (t == PS - 1) hidden_out[eb * PH + ej] = hnew;
        }
        __syncthreads();
        if (tid == 0) {
            asm volatile("red.release.gpu.global.add.u32 [%0], %1;"
                         :: "l"(&g_cnt), "r"(1u) : "memory");
        }

        // fc epilogue in the shadow of the next poll
        {
            float* pw = sp + warp * 512;
            pw[384 + fr * 8 + 2 * fc]           = fca[0];
            pw[384 + fr * 8 + 2 * fc + 1]       = fca[1];
            pw[384 + (fr + 8) * 8 + 2 * fc]     = fca[2];
            pw[384 + (fr + 8) * 8 + 2 * fc + 1] = fca[3];
        }
        __syncthreads();
        if (t > 0 && tid < 128) {
            float so = 0.f;
            #pragma unroll
            for (int w = 0; w < 8; w++) so += sp[w * 512 + 384 + tid];
            out[((size_t)eb * PS + (t - 1)) * PI + ej] = so + bias_fc;
        }
    }

    // ---- tail: fc for the final timestep (uses h(PS)) ----
    if (tid == 0) {
        const unsigned target = (unsigned)RG * (unsigned)PS;
        unsigned v;
        do {
            asm volatile("ld.acquire.gpu.global.u32 %0, [%1];"
                         : "=r"(v) : "l"(&g_cnt));
        } while (v < target);
    }
    __syncthreads();
    {
        const uint32_t* hb = (const uint32_t*)(&g_h16[PS & 1][0]);
        float acc[4] = {0.f, 0.f, 0.f, 0.f};
        #pragma unroll
        for (int ks = 0; ks < 8; ks++) {
            int q = warp * 64 + ks * 8 + fc;
            uint32_t a0 = __ldcg(hb + (size_t)fr * 512 + q);
            uint32_t a1 = __ldcg(hb + (size_t)(fr + 8) * 512 + q);
            uint32_t a2 = __ldcg(hb + (size_t)fr * 512 + q + 4);
            uint32_t a3 = __ldcg(hb + (size_t)(fr + 8) * 512 + q + 4);
            asm volatile(
                "mma.sync.aligned.m16n8k16.row.col.f32.f16.f16.f32 "
                "{%0,%1,%2,%3}, {%4,%5,%6,%7}, {%8,%9}, {%0,%1,%2,%3};"
                : "+f"(acc[0]), "+f"(acc[1]), "+f"(acc[2]), "+f"(acc[3])
                : "r"(a0), "r"(a1), "r"(a2), "r"(a3),
                  "r"(ff[ks][0]), "r"(ff[ks][1]));
        }
        float* pw = sp + warp * 512;
        pw[384 + fr * 8 + 2 * fc]           = acc[0];
        pw[384 + fr * 8 + 2 * fc + 1]       = acc[1];
        pw[384 + (fr + 8) * 8 + 2 * fc]     = acc[2];
        pw[384 + (fr + 8) * 8 + 2 * fc + 1] = acc[3];
    }
    __syncthreads();
    if (tid < 128) {
        float so = 0.f;
        #pragma unroll
        for (int w = 0; w < 8; w++) so += sp[w * 512 + 384 + tid];
        out[((size_t)eb * PS + (PS - 1)) * PI + ej] = so + bias_fc;
    }
}

// ---------------- attn = ones ------------------------------------------------
__global__ void fill_ones(float* __restrict__ p, int n)
{
    int i = blockIdx.x * blockDim.x + threadIdx.x;
    if (i < n) p[i] = 1.0f;
}

// ---------------- launch -----------------------------------------------------
extern "C" void kernel_launch(void* const* d_in, const int* in_sizes, int n_in,
                              void* d_out, int out_size)
{
    const float* x    = (const float*)d_in[0];
    // d_in[1..4] = attention params: dead (softmax over size-1 axis == 1)
    const float* w_ih = (const float*)d_in[5];
    const float* w_hh = (const float*)d_in[6];
    const float* b_ih = (const float*)d_in[7];
    const float* b_hh = (const float*)d_in[8];
    const float* fc_w = (const float*)d_in[9];
    const float* fc_b = (const float*)d_in[10];

    float* out    = (float*)d_out;                       // [B*S, I]
    float* hidden = out + (size_t)PB * PS * PI;          // [B, H]
    float* attn   = hidden + (size_t)PB * PH;            // [B*S]

    float *gi_ptr;
    __half *x16, *wih16;
    cudaGetSymbolAddress((void**)&gi_ptr, g_gi);
    cudaGetSymbolAddress((void**)&x16,    g_x16);
    cudaGetSymbolAddress((void**)&wih16,  g_wih16);

    const int M = PB * PS;   // 32768

    // 0) convert gi-GEMM operands to fp16
    to_half<<<1184, 256>>>(x,    x16,   (PB * PS * PI) / 4);
    to_half<<<296,  256>>>(w_ih, wih16, (3 * PH * PI) / 4);

    const size_t gsmem = 2 * (size_t)(2 * 128 * GP2) * sizeof(__half2); // 40KB
    cudaFuncSetAttribute(gemm_f16_bt_bias,
                         cudaFuncAttributeMaxDynamicSharedMemorySize, (int)gsmem);

    // 1) gi = x @ w_ih^T + b_ih   [32768, 3072] fp32
    {
        dim3 grid((3 * PH) / 128, M / 128);
        gemm_f16_bt_bias<<<grid, 256, gsmem>>>(x16, wih16, b_ih, gi_ptr,
                                               M, 3 * PH, PI);
    }

    // 2) persistent GRU scan + fused fc output
    gru_persistent_tc<<<RG, RTH>>>(gi_ptr, w_hh, b_hh, fc_w, fc_b, out, hidden);

    // 3) attn = 1.0
    {
        int n = PB * PS;
        fill_ones<<<(n + 255) / 256, 256>>>(attn, n);
    }
}